// round 2
// baseline (speedup 1.0000x reference)
#include <cuda_runtime.h>
#include <cuda_bf16.h>
#include <math.h>

// Problem constants
#define BATCH 2
#define SEQ 2048
#define DMODEL 2048
#define NHEADS 16
#define HEADDIM 128
#define CACHE 2048
#define TTOT 4096           // CACHE + SEQ
#define MROWS (BATCH*SEQ)   // 4096

// Scratch: Q projection (B,S,D) and attention output (B,S,D)
__device__ float g_q[MROWS * DMODEL];
__device__ float g_attn[MROWS * DMODEL];

// ---------------------------------------------------------------------------
// Cache copy: cached_k/v (B,H,CACHE,Dh) -> k_out/v_out (B,H,TTOT,Dh) rows [0,CACHE)
// ---------------------------------------------------------------------------
__global__ __launch_bounds__(256) void copy_cache_kernel(
    const float4* __restrict__ ck, const float4* __restrict__ cv,
    float4* __restrict__ ko, float4* __restrict__ vo)
{
    int i = blockIdx.x * blockDim.x + threadIdx.x;       // over BATCH*NHEADS*CACHE*HEADDIM/4
    const int N4 = BATCH * NHEADS * CACHE * HEADDIM / 4; // 2097152
    if (i >= N4) return;
    const int per_bh = CACHE * HEADDIM / 4;              // 65536
    int bh  = i / per_bh;
    int rem = i - bh * per_bh;
    long dst = (long)bh * (TTOT * HEADDIM / 4) + rem;
    ko[dst] = ck[i];
    vo[dst] = cv[i];
}

// ---------------------------------------------------------------------------
// Tiled NT GEMM: C[m,n] = sum_k A[m,k] * B[n,k]
// A: MxK row-major, B: NxK row-major.
// mode 0: C row-major MxN
// mode 1: scatter into (B,H,TTOT,Dh) at t = CACHE + s   (K/V projections)
// Tile 128x128x16, 256 threads, 8x8 micro-tile per thread.
// ---------------------------------------------------------------------------
__global__ __launch_bounds__(256) void gemm_nt_kernel(
    const float* __restrict__ A, const float* __restrict__ B,
    float* __restrict__ C, int M, int N, int K, int mode)
{
    __shared__ float As[16][128];
    __shared__ float Bs[16][128];

    const int tid = threadIdx.x;
    const int tx = tid & 15;
    const int ty = tid >> 4;
    const int m0 = blockIdx.y * 128;
    const int n0 = blockIdx.x * 128;

    const float* Ab = A + (long)m0 * K;
    const float* Bb = B + (long)n0 * K;

    float acc[8][8];
#pragma unroll
    for (int i = 0; i < 8; i++)
#pragma unroll
        for (int j = 0; j < 8; j++) acc[i][j] = 0.f;

    for (int k0 = 0; k0 < K; k0 += 16) {
        // Load A tile and B tile (transposed into [k][m/n])
#pragma unroll
        for (int it = 0; it < 2; it++) {
            int f   = tid + it * 256;  // 0..511
            int row = f >> 2;          // 0..127
            int c4  = f & 3;           // 0..3
            float4 a = *(const float4*)(Ab + (long)row * K + k0 + c4 * 4);
            As[c4 * 4 + 0][row] = a.x;
            As[c4 * 4 + 1][row] = a.y;
            As[c4 * 4 + 2][row] = a.z;
            As[c4 * 4 + 3][row] = a.w;
            float4 b = *(const float4*)(Bb + (long)row * K + k0 + c4 * 4);
            Bs[c4 * 4 + 0][row] = b.x;
            Bs[c4 * 4 + 1][row] = b.y;
            Bs[c4 * 4 + 2][row] = b.z;
            Bs[c4 * 4 + 3][row] = b.w;
        }
        __syncthreads();
#pragma unroll
        for (int kk = 0; kk < 16; kk++) {
            float af[8], bf[8];
            *(float4*)&af[0] = *(float4*)&As[kk][ty * 8];
            *(float4*)&af[4] = *(float4*)&As[kk][ty * 8 + 4];
            *(float4*)&bf[0] = *(float4*)&Bs[kk][tx * 8];
            *(float4*)&bf[4] = *(float4*)&Bs[kk][tx * 8 + 4];
#pragma unroll
            for (int i = 0; i < 8; i++)
#pragma unroll
                for (int j = 0; j < 8; j++)
                    acc[i][j] = fmaf(af[i], bf[j], acc[i][j]);
        }
        __syncthreads();
    }

    // Epilogue
    if (mode == 0) {
#pragma unroll
        for (int i = 0; i < 8; i++) {
            int m = m0 + ty * 8 + i;
            float* p = C + (long)m * N + n0 + tx * 8;
            float4 v0 = make_float4(acc[i][0], acc[i][1], acc[i][2], acc[i][3]);
            float4 v1 = make_float4(acc[i][4], acc[i][5], acc[i][6], acc[i][7]);
            ((float4*)p)[0] = v0;
            ((float4*)p)[1] = v1;
        }
    } else {
        int n  = n0 + tx * 8;
        int h  = n >> 7;        // / HEADDIM
        int dh = n & 127;
#pragma unroll
        for (int i = 0; i < 8; i++) {
            int m = m0 + ty * 8 + i;
            int b = m >> 11;    // / SEQ
            int s = m & 2047;
            float* p = C + ((long)(b * NHEADS + h) * TTOT + CACHE + s) * HEADDIM + dh;
            float4 v0 = make_float4(acc[i][0], acc[i][1], acc[i][2], acc[i][3]);
            float4 v1 = make_float4(acc[i][4], acc[i][5], acc[i][6], acc[i][7]);
            ((float4*)p)[0] = v0;
            ((float4*)p)[1] = v1;
        }
    }
}

// ---------------------------------------------------------------------------
// Flash attention (fp32). Q: (B,S,DMODEL) head-interleaved row-major.
// K,V: (B,H,TTOT,Dh). Output: (B,S,DMODEL) head-interleaved row-major.
// BM=64 query rows per CTA, BT=64 key rows per iter, full Dh=128.
// 256 threads (16x16). S-tile: 4x4/thread. O-tile: 4 rows x 8 cols/thread.
// ---------------------------------------------------------------------------
#define AT_SMEM_FLOATS (64*128 + 64*128 + 64*65 + 3*64)
#define AT_SMEM_BYTES (AT_SMEM_FLOATS * 4)

__global__ __launch_bounds__(256) void attn_kernel(
    const float* __restrict__ Q, const float* __restrict__ Kc,
    const float* __restrict__ Vc, float* __restrict__ Oa)
{
    extern __shared__ float sm[];
    float* Qs   = sm;               // [64][128]
    float* KVt  = Qs + 64 * 128;    // K transposed [128][64]  OR  V row-major [64][128]
    float* Ss   = KVt + 64 * 128;   // [64][65]
    float* mrow = Ss + 64 * 65;     // [64]
    float* lrow = mrow + 64;        // [64]
    float* arow = lrow + 64;        // [64]

    const int bh = blockIdx.y;      // b*NHEADS + h
    const int b  = bh >> 4;
    const int h  = bh & 15;
    const int s0 = blockIdx.x * 64;
    const int tid = threadIdx.x;
    const int tx = tid & 15;
    const int ty = tid >> 4;
    const int warp = tid >> 5;
    const int lane = tid & 31;

    const float scale = 0.08838834764831845f;  // 1/sqrt(128)

    // Load Q tile: 64 rows x 128 cols, row stride DMODEL
    const float* qbase = Q + ((long)b * SEQ + s0) * DMODEL + h * HEADDIM;
    for (int i = tid; i < 64 * 32; i += 256) {
        int r = i >> 5, c4 = i & 31;
        float4 v = *(const float4*)(qbase + (long)r * DMODEL + c4 * 4);
        *(float4*)(Qs + r * 128 + c4 * 4) = v;
    }
    if (tid < 64) { mrow[tid] = -INFINITY; lrow[tid] = 0.f; }

    float o_acc[4][8];
#pragma unroll
    for (int i = 0; i < 4; i++)
#pragma unroll
        for (int j = 0; j < 8; j++) o_acc[i][j] = 0.f;

    const float* kbase = Kc + (long)bh * TTOT * HEADDIM;
    const float* vbase = Vc + (long)bh * TTOT * HEADDIM;

    for (int t0 = 0; t0 < TTOT; t0 += 64) {
        __syncthreads();  // KVt reuse hazard + first-iter Q/stats readiness

        // Load K tile transposed: KVt[d][c]
        for (int i = tid; i < 64 * 32; i += 256) {
            int r = i >> 5, c4 = i & 31;
            float4 v = *(const float4*)(kbase + (long)(t0 + r) * HEADDIM + c4 * 4);
            KVt[(c4 * 4 + 0) * 64 + r] = v.x;
            KVt[(c4 * 4 + 1) * 64 + r] = v.y;
            KVt[(c4 * 4 + 2) * 64 + r] = v.z;
            KVt[(c4 * 4 + 3) * 64 + r] = v.w;
        }
        __syncthreads();

        // S tile: thread (ty,tx) -> rows ty*4..+3, cols tx*4..+3
        float s_acc[4][4];
#pragma unroll
        for (int i = 0; i < 4; i++)
#pragma unroll
            for (int j = 0; j < 4; j++) s_acc[i][j] = 0.f;

        for (int d = 0; d < 128; d++) {
            float4 k4 = *(float4*)(KVt + d * 64 + tx * 4);
            float kf[4] = {k4.x, k4.y, k4.z, k4.w};
#pragma unroll
            for (int i = 0; i < 4; i++) {
                float qv = Qs[(ty * 4 + i) * 128 + d];
#pragma unroll
                for (int j = 0; j < 4; j++)
                    s_acc[i][j] = fmaf(qv, kf[j], s_acc[i][j]);
            }
        }
#pragma unroll
        for (int i = 0; i < 4; i++)
#pragma unroll
            for (int j = 0; j < 4; j++)
                Ss[(ty * 4 + i) * 65 + tx * 4 + j] = s_acc[i][j] * scale;
        __syncthreads();  // Ss ready; K no longer needed

        // Load V tile (row-major) into KVt
        for (int i = tid; i < 64 * 32; i += 256) {
            int r = i >> 5, c4 = i & 31;
            float4 v = *(const float4*)(vbase + (long)(t0 + r) * HEADDIM + c4 * 4);
            *(float4*)(KVt + r * 128 + c4 * 4) = v;
        }

        // Online softmax: warp w handles rows w*8 .. w*8+7
        for (int rr = 0; rr < 8; rr++) {
            int r = warp * 8 + rr;
            float x0 = Ss[r * 65 + lane];
            float x1 = Ss[r * 65 + 32 + lane];
            float mx = fmaxf(x0, x1);
#pragma unroll
            for (int off = 16; off; off >>= 1)
                mx = fmaxf(mx, __shfl_xor_sync(0xffffffffu, mx, off));
            float m_old = mrow[r];
            float m_new = fmaxf(m_old, mx);
            float e0 = __expf(x0 - m_new);
            float e1 = __expf(x1 - m_new);
            Ss[r * 65 + lane] = e0;
            Ss[r * 65 + 32 + lane] = e1;
            float sum = e0 + e1;
#pragma unroll
            for (int off = 16; off; off >>= 1)
                sum += __shfl_xor_sync(0xffffffffu, sum, off);
            if (lane == 0) {
                float alpha = __expf(m_old - m_new);
                arow[r] = alpha;
                lrow[r] = lrow[r] * alpha + sum;
                mrow[r] = m_new;
            }
        }
        __syncthreads();  // P + V + alpha ready

        // Rescale O and accumulate P @ V
        float al[4];
#pragma unroll
        for (int i = 0; i < 4; i++) al[i] = arow[ty * 4 + i];
#pragma unroll
        for (int i = 0; i < 4; i++)
#pragma unroll
            for (int j = 0; j < 8; j++) o_acc[i][j] *= al[i];

        for (int t = 0; t < 64; t++) {
            float4 v0 = *(float4*)(KVt + t * 128 + tx * 8);
            float4 v1 = *(float4*)(KVt + t * 128 + tx * 8 + 4);
            float vf[8] = {v0.x, v0.y, v0.z, v0.w, v1.x, v1.y, v1.z, v1.w};
#pragma unroll
            for (int i = 0; i < 4; i++) {
                float p = Ss[(ty * 4 + i) * 65 + t];
#pragma unroll
                for (int j = 0; j < 8; j++)
                    o_acc[i][j] = fmaf(p, vf[j], o_acc[i][j]);
            }
        }
    }

    // Final normalize + store (head-interleaved (B,S,DMODEL))
#pragma unroll
    for (int i = 0; i < 4; i++) {
        int r = ty * 4 + i;
        float inv = 1.f / lrow[r];
        float* p = Oa + ((long)b * SEQ + s0 + r) * DMODEL + h * HEADDIM + tx * 8;
        float4 v0 = make_float4(o_acc[i][0] * inv, o_acc[i][1] * inv,
                                o_acc[i][2] * inv, o_acc[i][3] * inv);
        float4 v1 = make_float4(o_acc[i][4] * inv, o_acc[i][5] * inv,
                                o_acc[i][6] * inv, o_acc[i][7] * inv);
        ((float4*)p)[0] = v0;
        ((float4*)p)[1] = v1;
    }
}

// ---------------------------------------------------------------------------
// kernel_launch
// Inputs (metadata order): x, cached_k, cached_v, W_q, W_k, W_v, W_o
// Output buffer: [ out (B,S,D) | k (B,H,TTOT,Dh) | v (B,H,TTOT,Dh) ]
// ---------------------------------------------------------------------------
extern "C" void kernel_launch(void* const* d_in, const int* in_sizes, int n_in,
                              void* d_out, int out_size)
{
    const float* x  = (const float*)d_in[0];
    const float* ck = (const float*)d_in[1];
    const float* cv = (const float*)d_in[2];
    const float* wq = (const float*)d_in[3];
    const float* wk = (const float*)d_in[4];
    const float* wv = (const float*)d_in[5];
    const float* wo = (const float*)d_in[6];

    float* out   = (float*)d_out;
    float* k_out = out + (long)MROWS * DMODEL;                       // 8388608
    float* v_out = k_out + (long)BATCH * NHEADS * TTOT * HEADDIM;    // +16777216

    float* qs;  cudaGetSymbolAddress((void**)&qs, g_q);
    float* at;  cudaGetSymbolAddress((void**)&at, g_attn);

    // 1) copy KV cache into outputs
    {
        const int N4 = BATCH * NHEADS * CACHE * HEADDIM / 4;
        copy_cache_kernel<<<(N4 + 255) / 256, 256>>>(
            (const float4*)ck, (const float4*)cv, (float4*)k_out, (float4*)v_out);
    }

    // 2) Q, K, V projections
    dim3 gg(DMODEL / 128, MROWS / 128);  // (16, 32)
    gemm_nt_kernel<<<gg, 256>>>(x, wq, qs,    MROWS, DMODEL, DMODEL, 0);
    gemm_nt_kernel<<<gg, 256>>>(x, wk, k_out, MROWS, DMODEL, DMODEL, 1);
    gemm_nt_kernel<<<gg, 256>>>(x, wv, v_out, MROWS, DMODEL, DMODEL, 1);

    // 3) attention
    cudaFuncSetAttribute(attn_kernel, cudaFuncAttributeMaxDynamicSharedMemorySize,
                         AT_SMEM_BYTES);
    attn_kernel<<<dim3(SEQ / 64, BATCH * NHEADS), 256, AT_SMEM_BYTES>>>(
        qs, k_out, v_out, at);

    // 4) output projection
    gemm_nt_kernel<<<gg, 256>>>(at, wo, out, MROWS, DMODEL, DMODEL, 0);
}

// round 3
// speedup vs baseline: 1.2404x; 1.2404x over previous
#include <cuda_runtime.h>
#include <cuda_bf16.h>
#include <math.h>

// Problem constants
#define BATCH 2
#define SEQ 2048
#define DMODEL 2048
#define NHEADS 16
#define HEADDIM 128
#define CACHE 2048
#define TTOT 4096           // CACHE + SEQ
#define MROWS (BATCH*SEQ)   // 4096

// Scratch: Q projection (B,S,D) and attention output (B,S,D)
__device__ float g_q[MROWS * DMODEL];
__device__ float g_attn[MROWS * DMODEL];

// ---------------------------------------------------------------------------
// Cache copy: cached_k/v (B,H,CACHE,Dh) -> k_out/v_out (B,H,TTOT,Dh) rows [0,CACHE)
// ---------------------------------------------------------------------------
__global__ __launch_bounds__(256) void copy_cache_kernel(
    const float4* __restrict__ ck, const float4* __restrict__ cv,
    float4* __restrict__ ko, float4* __restrict__ vo)
{
    int i = blockIdx.x * blockDim.x + threadIdx.x;
    const int N4 = BATCH * NHEADS * CACHE * HEADDIM / 4;
    if (i >= N4) return;
    const int per_bh = CACHE * HEADDIM / 4;
    int bh  = i / per_bh;
    int rem = i - bh * per_bh;
    long dst = (long)bh * (TTOT * HEADDIM / 4) + rem;
    ko[dst] = ck[i];
    vo[dst] = cv[i];
}

// ---------------------------------------------------------------------------
// Tiled NT GEMM, double-buffered: C[m,n] = sum_k A[m,k]*B[n,k]
// Tile 128x128x16, 256 threads, 8x8 micro-tile. One barrier per k-chunk.
// mode 0: C row-major MxN ; mode 1: scatter into (B,H,TTOT,Dh) at t=CACHE+s
// ---------------------------------------------------------------------------
__global__ __launch_bounds__(256, 2) void gemm_nt_kernel(
    const float* __restrict__ A, const float* __restrict__ B,
    float* __restrict__ C, int M, int N, int K, int mode)
{
    __shared__ float As[2][16][128];
    __shared__ float Bs[2][16][128];

    const int tid = threadIdx.x;
    const int tx = tid & 15;
    const int ty = tid >> 4;
    const int m0 = blockIdx.y * 128;
    const int n0 = blockIdx.x * 128;

    // Each thread loads 2 float4 of A and 2 of B per chunk:
    // f = tid + it*256 -> row = f>>2 (0..127), c4 = f&3
    const int row0 = tid >> 2;
    const int row1 = (tid + 256) >> 2;
    const int c40  = tid & 3;
    const float* Ab = A + (long)m0 * K;
    const float* Bb = B + (long)n0 * K;

    float acc[8][8];
#pragma unroll
    for (int i = 0; i < 8; i++)
#pragma unroll
        for (int j = 0; j < 8; j++) acc[i][j] = 0.f;

    // Prologue: load chunk 0 directly
    {
        float4 a0 = *(const float4*)(Ab + (long)row0 * K + c40 * 4);
        float4 a1 = *(const float4*)(Ab + (long)row1 * K + c40 * 4);
        float4 b0 = *(const float4*)(Bb + (long)row0 * K + c40 * 4);
        float4 b1 = *(const float4*)(Bb + (long)row1 * K + c40 * 4);
        As[0][c40*4+0][row0] = a0.x; As[0][c40*4+1][row0] = a0.y;
        As[0][c40*4+2][row0] = a0.z; As[0][c40*4+3][row0] = a0.w;
        As[0][c40*4+0][row1] = a1.x; As[0][c40*4+1][row1] = a1.y;
        As[0][c40*4+2][row1] = a1.z; As[0][c40*4+3][row1] = a1.w;
        Bs[0][c40*4+0][row0] = b0.x; Bs[0][c40*4+1][row0] = b0.y;
        Bs[0][c40*4+2][row0] = b0.z; Bs[0][c40*4+3][row0] = b0.w;
        Bs[0][c40*4+0][row1] = b1.x; Bs[0][c40*4+1][row1] = b1.y;
        Bs[0][c40*4+2][row1] = b1.z; Bs[0][c40*4+3][row1] = b1.w;
    }
    __syncthreads();

    int cur = 0;
    for (int k0 = 0; k0 < K; k0 += 16) {
        // Prefetch next chunk into registers
        float4 pa0, pa1, pb0, pb1;
        const bool more = (k0 + 16) < K;
        if (more) {
            int kn = k0 + 16;
            pa0 = *(const float4*)(Ab + (long)row0 * K + kn + c40 * 4);
            pa1 = *(const float4*)(Ab + (long)row1 * K + kn + c40 * 4);
            pb0 = *(const float4*)(Bb + (long)row0 * K + kn + c40 * 4);
            pb1 = *(const float4*)(Bb + (long)row1 * K + kn + c40 * 4);
        }

        // Compute on current buffer
#pragma unroll
        for (int kk = 0; kk < 16; kk++) {
            float af[8], bf[8];
            *(float4*)&af[0] = *(float4*)&As[cur][kk][ty * 8];
            *(float4*)&af[4] = *(float4*)&As[cur][kk][ty * 8 + 4];
            *(float4*)&bf[0] = *(float4*)&Bs[cur][kk][tx * 8];
            *(float4*)&bf[4] = *(float4*)&Bs[cur][kk][tx * 8 + 4];
#pragma unroll
            for (int i = 0; i < 8; i++)
#pragma unroll
                for (int j = 0; j < 8; j++)
                    acc[i][j] = fmaf(af[i], bf[j], acc[i][j]);
        }

        if (more) {
            int nxt = cur ^ 1;
            As[nxt][c40*4+0][row0] = pa0.x; As[nxt][c40*4+1][row0] = pa0.y;
            As[nxt][c40*4+2][row0] = pa0.z; As[nxt][c40*4+3][row0] = pa0.w;
            As[nxt][c40*4+0][row1] = pa1.x; As[nxt][c40*4+1][row1] = pa1.y;
            As[nxt][c40*4+2][row1] = pa1.z; As[nxt][c40*4+3][row1] = pa1.w;
            Bs[nxt][c40*4+0][row0] = pb0.x; Bs[nxt][c40*4+1][row0] = pb0.y;
            Bs[nxt][c40*4+2][row0] = pb0.z; Bs[nxt][c40*4+3][row0] = pb0.w;
            Bs[nxt][c40*4+0][row1] = pb1.x; Bs[nxt][c40*4+1][row1] = pb1.y;
            Bs[nxt][c40*4+2][row1] = pb1.z; Bs[nxt][c40*4+3][row1] = pb1.w;
        }
        __syncthreads();
        cur ^= 1;
    }

    // Epilogue
    if (mode == 0) {
#pragma unroll
        for (int i = 0; i < 8; i++) {
            int m = m0 + ty * 8 + i;
            float* p = C + (long)m * N + n0 + tx * 8;
            ((float4*)p)[0] = make_float4(acc[i][0], acc[i][1], acc[i][2], acc[i][3]);
            ((float4*)p)[1] = make_float4(acc[i][4], acc[i][5], acc[i][6], acc[i][7]);
        }
    } else {
        int n  = n0 + tx * 8;
        int h  = n >> 7;
        int dh = n & 127;
#pragma unroll
        for (int i = 0; i < 8; i++) {
            int m = m0 + ty * 8 + i;
            int b = m >> 11;
            int s = m & 2047;
            float* p = C + ((long)(b * NHEADS + h) * TTOT + CACHE + s) * HEADDIM + dh;
            ((float4*)p)[0] = make_float4(acc[i][0], acc[i][1], acc[i][2], acc[i][3]);
            ((float4*)p)[1] = make_float4(acc[i][4], acc[i][5], acc[i][6], acc[i][7]);
        }
    }
}

// ---------------------------------------------------------------------------
// Flash attention (fp32), BM=128 query rows, BT=128 key rows per iter.
// 256 threads (16x16 grid), 8x8 microtiles for S=QK^T and O+=P@V.
// Q and K held transposed [d][m]/[d][t] with stride 132 (conflict-free).
// Register-resident online softmax with shfl row reductions.
// ---------------------------------------------------------------------------
#define AT_STRIDE 132
#define AT_SMEM_FLOATS (128*AT_STRIDE /*Qt*/ + 128*AT_STRIDE /*Kt or V*/ \
                        + 128*AT_STRIDE /*Ss*/ + 2*128)
#define AT_SMEM_BYTES (AT_SMEM_FLOATS * 4)

__global__ __launch_bounds__(256) void attn_kernel(
    const float* __restrict__ Q, const float* __restrict__ Kc,
    const float* __restrict__ Vc, float* __restrict__ Oa)
{
    extern __shared__ float sm[];
    float* Qt   = sm;                     // [128 d][132] (cols = m)
    float* KV   = Qt + 128 * AT_STRIDE;   // Kt [128 d][132] (cols = t)  OR  V [128 t][128 d]
    float* Ss   = KV + 128 * AT_STRIDE;   // P: [128 m][132] (cols = t)
    float* mrow = Ss + 128 * AT_STRIDE;   // [128]
    float* lrow = mrow + 128;             // [128]

    const int bh = blockIdx.y;
    const int b  = bh >> 4;
    const int h  = bh & 15;
    const int s0 = blockIdx.x * 128;
    const int tid = threadIdx.x;
    const int tx = tid & 15;
    const int ty = tid >> 4;

    const float scale = 0.08838834764831845f;  // 1/sqrt(128)

    // Load Q tile transposed: Qt[d][m]. Per-lane distinct m -> conflict-free STS.
    const float* qbase = Q + ((long)b * SEQ + s0) * DMODEL + h * HEADDIM;
    for (int i = tid; i < 128 * 32; i += 256) {
        int c4 = i >> 7;       // 0..31 (d/4)
        int m  = i & 127;
        float4 v = *(const float4*)(qbase + (long)m * DMODEL + c4 * 4);
        Qt[(c4 * 4 + 0) * AT_STRIDE + m] = v.x;
        Qt[(c4 * 4 + 1) * AT_STRIDE + m] = v.y;
        Qt[(c4 * 4 + 2) * AT_STRIDE + m] = v.z;
        Qt[(c4 * 4 + 3) * AT_STRIDE + m] = v.w;
    }
    if (tid < 128) { mrow[tid] = -INFINITY; lrow[tid] = 0.f; }

    float o_acc[8][8];
#pragma unroll
    for (int i = 0; i < 8; i++)
#pragma unroll
        for (int j = 0; j < 8; j++) o_acc[i][j] = 0.f;

    const float* kbase = Kc + (long)bh * TTOT * HEADDIM;
    const float* vbase = Vc + (long)bh * TTOT * HEADDIM;

    for (int t0 = 0; t0 < TTOT; t0 += 128) {
        __syncthreads();  // prior iter done with KV (V) and Ss; Qt ready on iter 0

        // Load K tile transposed: KV[d][t]
        for (int i = tid; i < 128 * 32; i += 256) {
            int c4 = i >> 7;
            int t  = i & 127;
            float4 v = *(const float4*)(kbase + (long)(t0 + t) * HEADDIM + c4 * 4);
            KV[(c4 * 4 + 0) * AT_STRIDE + t] = v.x;
            KV[(c4 * 4 + 1) * AT_STRIDE + t] = v.y;
            KV[(c4 * 4 + 2) * AT_STRIDE + t] = v.z;
            KV[(c4 * 4 + 3) * AT_STRIDE + t] = v.w;
        }
        __syncthreads();

        // S = Q K^T : 8x8 microtile, rows m0+ty*8.., cols t0+tx*8..
        float s_acc[8][8];
#pragma unroll
        for (int i = 0; i < 8; i++)
#pragma unroll
            for (int j = 0; j < 8; j++) s_acc[i][j] = 0.f;

        for (int d = 0; d < 128; d++) {
            float af[8], bf[8];
            *(float4*)&af[0] = *(float4*)(Qt + d * AT_STRIDE + ty * 8);
            *(float4*)&af[4] = *(float4*)(Qt + d * AT_STRIDE + ty * 8 + 4);
            *(float4*)&bf[0] = *(float4*)(KV + d * AT_STRIDE + tx * 8);
            *(float4*)&bf[4] = *(float4*)(KV + d * AT_STRIDE + tx * 8 + 4);
#pragma unroll
            for (int i = 0; i < 8; i++)
#pragma unroll
                for (int j = 0; j < 8; j++)
                    s_acc[i][j] = fmaf(af[i], bf[j], s_acc[i][j]);
        }
#pragma unroll
        for (int i = 0; i < 8; i++)
#pragma unroll
            for (int j = 0; j < 8; j++) s_acc[i][j] *= scale;

        __syncthreads();  // all lanes done reading KV (Kt) -> safe to overwrite with V

        // Load V tile row-major into KV: V[t][d], stride 128
        for (int i = tid; i < 128 * 32; i += 256) {
            int t  = i >> 5;
            int c4 = i & 31;
            float4 v = *(const float4*)(vbase + (long)(t0 + t) * HEADDIM + c4 * 4);
            *(float4*)(KV + t * 128 + c4 * 4) = v;
        }

        // Online softmax in registers. Row r = ty*8+i owned by the 16 lanes of ty
        // (one half-warp). Row reduction over tx via shfl_xor of lane bits 0..3.
        float alpha[8];
#pragma unroll
        for (int i = 0; i < 8; i++) {
            float mx = s_acc[i][0];
#pragma unroll
            for (int j = 1; j < 8; j++) mx = fmaxf(mx, s_acc[i][j]);
#pragma unroll
            for (int off = 8; off; off >>= 1)
                mx = fmaxf(mx, __shfl_xor_sync(0xffffffffu, mx, off));
            int r = ty * 8 + i;
            float m_old = mrow[r];
            float m_new = fmaxf(m_old, mx);
            alpha[i] = __expf(m_old - m_new);
            float sum = 0.f;
#pragma unroll
            for (int j = 0; j < 8; j++) {
                float e = __expf(s_acc[i][j] - m_new);
                s_acc[i][j] = e;
                sum += e;
            }
#pragma unroll
            for (int off = 8; off; off >>= 1)
                sum += __shfl_xor_sync(0xffffffffu, sum, off);
            if (tx == 0) {  // converged warp: writes ordered after all lanes' reads
                lrow[r] = lrow[r] * alpha[i] + sum;
                mrow[r] = m_new;
            }
            // Write P row segment
            *(float4*)(Ss + r * AT_STRIDE + tx * 8) =
                make_float4(s_acc[i][0], s_acc[i][1], s_acc[i][2], s_acc[i][3]);
            *(float4*)(Ss + r * AT_STRIDE + tx * 8 + 4) =
                make_float4(s_acc[i][4], s_acc[i][5], s_acc[i][6], s_acc[i][7]);
        }
        __syncthreads();  // Ss + V visible

        // Rescale O and accumulate P @ V (8 rows x 8 d-cols per thread)
#pragma unroll
        for (int i = 0; i < 8; i++)
#pragma unroll
            for (int j = 0; j < 8; j++) o_acc[i][j] *= alpha[i];

        for (int t = 0; t < 128; t++) {
            float vf[8];
            *(float4*)&vf[0] = *(float4*)(KV + t * 128 + tx * 8);
            *(float4*)&vf[4] = *(float4*)(KV + t * 128 + tx * 8 + 4);
#pragma unroll
            for (int i = 0; i < 8; i++) {
                float p = Ss[(ty * 8 + i) * AT_STRIDE + t];
#pragma unroll
                for (int j = 0; j < 8; j++)
                    o_acc[i][j] = fmaf(p, vf[j], o_acc[i][j]);
            }
        }
    }

    // Final normalize + store (head-interleaved (B,S,DMODEL))
#pragma unroll
    for (int i = 0; i < 8; i++) {
        int r = ty * 8 + i;
        float inv = 1.f / lrow[r];
        float* p = Oa + ((long)b * SEQ + s0 + r) * DMODEL + h * HEADDIM + tx * 8;
        ((float4*)p)[0] = make_float4(o_acc[i][0]*inv, o_acc[i][1]*inv,
                                      o_acc[i][2]*inv, o_acc[i][3]*inv);
        ((float4*)p)[1] = make_float4(o_acc[i][4]*inv, o_acc[i][5]*inv,
                                      o_acc[i][6]*inv, o_acc[i][7]*inv);
    }
}

// ---------------------------------------------------------------------------
// kernel_launch
// Inputs: x, cached_k, cached_v, W_q, W_k, W_v, W_o
// Output: [ out (B,S,D) | k (B,H,TTOT,Dh) | v (B,H,TTOT,Dh) ]
// ---------------------------------------------------------------------------
extern "C" void kernel_launch(void* const* d_in, const int* in_sizes, int n_in,
                              void* d_out, int out_size)
{
    const float* x  = (const float*)d_in[0];
    const float* ck = (const float*)d_in[1];
    const float* cv = (const float*)d_in[2];
    const float* wq = (const float*)d_in[3];
    const float* wk = (const float*)d_in[4];
    const float* wv = (const float*)d_in[5];
    const float* wo = (const float*)d_in[6];

    float* out   = (float*)d_out;
    float* k_out = out + (long)MROWS * DMODEL;
    float* v_out = k_out + (long)BATCH * NHEADS * TTOT * HEADDIM;

    float* qs;  cudaGetSymbolAddress((void**)&qs, g_q);
    float* at;  cudaGetSymbolAddress((void**)&at, g_attn);

    // 1) copy KV cache into outputs
    {
        const int N4 = BATCH * NHEADS * CACHE * HEADDIM / 4;
        copy_cache_kernel<<<(N4 + 255) / 256, 256>>>(
            (const float4*)ck, (const float4*)cv, (float4*)k_out, (float4*)v_out);
    }

    // 2) Q, K, V projections
    dim3 gg(DMODEL / 128, MROWS / 128);  // (16, 32)
    gemm_nt_kernel<<<gg, 256>>>(x, wq, qs,    MROWS, DMODEL, DMODEL, 0);
    gemm_nt_kernel<<<gg, 256>>>(x, wk, k_out, MROWS, DMODEL, DMODEL, 1);
    gemm_nt_kernel<<<gg, 256>>>(x, wv, v_out, MROWS, DMODEL, DMODEL, 1);

    // 3) attention
    cudaFuncSetAttribute(attn_kernel, cudaFuncAttributeMaxDynamicSharedMemorySize,
                         AT_SMEM_BYTES);
    attn_kernel<<<dim3(SEQ / 128, BATCH * NHEADS), 256, AT_SMEM_BYTES>>>(
        qs, k_out, v_out, at);

    // 4) output projection
    gemm_nt_kernel<<<gg, 256>>>(at, wo, out, MROWS, DMODEL, DMODEL, 0);
}

// round 6
// speedup vs baseline: 1.6140x; 1.3012x over previous
#include <cuda_runtime.h>
#include <cuda_bf16.h>
#include <math.h>
#include <stdint.h>

// Problem constants
#define BATCH 2
#define SEQ 2048
#define DMODEL 2048
#define NHEADS 16
#define HEADDIM 128
#define CACHE 2048
#define TTOT 4096           // CACHE + SEQ
#define MROWS (BATCH*SEQ)   // 4096

// ---------------------------------------------------------------------------
// Scratch (device globals; no allocations allowed)
// ---------------------------------------------------------------------------
__device__ float g_q[MROWS * DMODEL];
__device__ float g_attn[MROWS * DMODEL];
__device__ __nv_bfloat16 g_ah[MROWS * DMODEL];   // activation hi (x, later attn-out)
__device__ __nv_bfloat16 g_al[MROWS * DMODEL];   // activation lo
__device__ __nv_bfloat16 g_wh[4][DMODEL * DMODEL];
__device__ __nv_bfloat16 g_wl[4][DMODEL * DMODEL];

// ---------------------------------------------------------------------------
// Helpers
// ---------------------------------------------------------------------------
__device__ __forceinline__ uint32_t smem_u32(const void* p) {
    uint32_t a;
    asm("{ .reg .u64 t; cvta.to.shared.u64 t, %1; cvt.u32.u64 %0, t; }" : "=r"(a) : "l"(p));
    return a;
}
__device__ __forceinline__ void cp16(void* dst_smem, const void* src) {
    uint32_t d = smem_u32(dst_smem);
    asm volatile("cp.async.cg.shared.global [%0], [%1], 16;" :: "r"(d), "l"(src) : "memory");
}
__device__ __forceinline__ void cp_commit() {
    asm volatile("cp.async.commit_group;" ::: "memory");
}
__device__ __forceinline__ void cp_wait1() {
    asm volatile("cp.async.wait_group 1;" ::: "memory");
}
__device__ __forceinline__ void cp_wait0() {
    asm volatile("cp.async.wait_group 0;" ::: "memory");
}
// D += A*B : m16n8k16 bf16, fp32 accum
__device__ __forceinline__ void mma16816(float* c, const uint32_t* a, const uint32_t* b) {
    asm volatile(
        "mma.sync.aligned.m16n8k16.row.col.f32.bf16.bf16.f32 "
        "{%0,%1,%2,%3}, {%4,%5,%6,%7}, {%8,%9}, {%0,%1,%2,%3};"
        : "+f"(c[0]), "+f"(c[1]), "+f"(c[2]), "+f"(c[3])
        : "r"(a[0]), "r"(a[1]), "r"(a[2]), "r"(a[3]), "r"(b[0]), "r"(b[1]));
}

// ---------------------------------------------------------------------------
// fp32 -> bf16 hi/lo split
// ---------------------------------------------------------------------------
__global__ __launch_bounds__(256) void split_kernel(
    const float4* __restrict__ in, __nv_bfloat16* __restrict__ hi,
    __nv_bfloat16* __restrict__ lo, int n4)
{
    int i = blockIdx.x * blockDim.x + threadIdx.x;
    if (i >= n4) return;
    float4 v = in[i];
    union { __nv_bfloat16 h[4]; uint2 u; } H, L;
    float f[4] = {v.x, v.y, v.z, v.w};
#pragma unroll
    for (int j = 0; j < 4; j++) {
        __nv_bfloat16 h = __float2bfloat16_rn(f[j]);
        H.h[j] = h;
        L.h[j] = __float2bfloat16_rn(f[j] - __bfloat162float(h));
    }
    *(uint2*)(hi + (long)i * 4) = H.u;
    *(uint2*)(lo + (long)i * 4) = L.u;
}

// ---------------------------------------------------------------------------
// Cache copy: cached_k/v -> k_out/v_out rows [0,CACHE)
// ---------------------------------------------------------------------------
__global__ __launch_bounds__(256) void copy_cache_kernel(
    const float4* __restrict__ ck, const float4* __restrict__ cv,
    float4* __restrict__ ko, float4* __restrict__ vo)
{
    int i = blockIdx.x * blockDim.x + threadIdx.x;
    const int N4 = BATCH * NHEADS * CACHE * HEADDIM / 4;
    if (i >= N4) return;
    const int per_bh = CACHE * HEADDIM / 4;
    int bh  = i / per_bh;
    int rem = i - bh * per_bh;
    long dst = (long)bh * (TTOT * HEADDIM / 4) + rem;
    ko[dst] = ck[i];
    vo[dst] = cv[i];
}

// ---------------------------------------------------------------------------
// HMMA GEMM: C[m,n] = sum_k A[m,k]*B[n,k]  (fp32 via bf16 hi/lo, 3 MMAs)
// CTA tile 128x128, K-chunk 32, cp.async double buffer.
// 8 warps = 2(M) x 4(N); warp tile 64x32 = 4 m16-tiles x 4 n8-tiles.
// SMEM per buffer: 4 matrices [128 rows][32 cols bf16], row stride 80 bytes.
// mode 0: C row-major MxN. mode 1: scatter to (B,H,TTOT,Dh) at t=CACHE+s.
// ---------------------------------------------------------------------------
#define GM_RS    80          // row stride bytes (40 bf16) -> conflict-free
#define GM_MAT   (128 * GM_RS)   // 10240 B per matrix tile
#define GM_BUF   (4 * GM_MAT)    // 40960 B per buffer
#define GM_SMEM  (2 * GM_BUF)    // 81920 B
#define GM_KCH   64              // 2048 / 32 chunks

__device__ __forceinline__ void gm_issue_chunk(
    char* buf, const __nv_bfloat16* Ah, const __nv_bfloat16* Al,
    const __nv_bfloat16* Bh, const __nv_bfloat16* Bl,
    long m0, long n0, int k0, int tid)
{
    const int row = tid >> 2;      // 0..63
    const int seg = tid & 3;       // 16B segment within 64B row
#pragma unroll
    for (int it = 0; it < 2; it++) {
        int rr = row + it * 64;
        long off = (long)k0 + seg * 8;
        cp16(buf + 0 * GM_MAT + rr * GM_RS + seg * 16, Ah + (m0 + rr) * DMODEL + off);
        cp16(buf + 1 * GM_MAT + rr * GM_RS + seg * 16, Al + (m0 + rr) * DMODEL + off);
        cp16(buf + 2 * GM_MAT + rr * GM_RS + seg * 16, Bh + (n0 + rr) * DMODEL + off);
        cp16(buf + 3 * GM_MAT + rr * GM_RS + seg * 16, Bl + (n0 + rr) * DMODEL + off);
    }
    cp_commit();
}

__global__ __launch_bounds__(256, 1)
void gemm_tc_kernel(const __nv_bfloat16* __restrict__ Ah,
                    const __nv_bfloat16* __restrict__ Al,
                    const __nv_bfloat16* __restrict__ Bh,
                    const __nv_bfloat16* __restrict__ Bl,
                    float* __restrict__ C, int mode)
{
    extern __shared__ char dsm[];
    const int tid  = threadIdx.x;
    const int wid  = tid >> 5;
    const int lane = tid & 31;
    const int wm   = wid >> 2;          // 0..1
    const int wn   = wid & 3;           // 0..3
    const long m0 = (long)blockIdx.y * 128;
    const long n0 = (long)blockIdx.x * 128;

    const int fr = lane >> 2;           // fragment row 0..7
    const int fq = (lane & 3) * 2;      // fragment col pair base

    float acc[4][4][4];
#pragma unroll
    for (int i = 0; i < 4; i++)
#pragma unroll
        for (int j = 0; j < 4; j++)
#pragma unroll
            for (int t = 0; t < 4; t++) acc[i][j][t] = 0.f;

    // prologue: chunk 0 into buf 0
    gm_issue_chunk(dsm, Ah, Al, Bh, Bl, m0, n0, 0, tid);

    for (int c = 0; c < GM_KCH; c++) {
        if (c + 1 < GM_KCH)
            gm_issue_chunk(dsm + ((c + 1) & 1) * GM_BUF, Ah, Al, Bh, Bl,
                           m0, n0, (c + 1) * 32, tid);
        if (c + 1 < GM_KCH) cp_wait1(); else cp_wait0();
        __syncthreads();

        const char* sb  = dsm + (c & 1) * GM_BUF;
        const char* sAh = sb;
        const char* sAl = sb + GM_MAT;
        const char* sBh = sb + 2 * GM_MAT;
        const char* sBl = sb + 3 * GM_MAT;

#pragma unroll
        for (int kk = 0; kk < 32; kk += 16) {
            uint32_t ah[4][4], al[4][4], bh[4][2], bl[4][2];
#pragma unroll
            for (int mt = 0; mt < 4; mt++) {
                int row0 = wm * 64 + mt * 16 + fr;
                const char* pa = sAh + row0 * GM_RS + (kk + fq) * 2;
                const char* pl = sAl + row0 * GM_RS + (kk + fq) * 2;
                ah[mt][0] = *(const uint32_t*)(pa);
                ah[mt][1] = *(const uint32_t*)(pa + 8 * GM_RS);
                ah[mt][2] = *(const uint32_t*)(pa + 16);
                ah[mt][3] = *(const uint32_t*)(pa + 8 * GM_RS + 16);
                al[mt][0] = *(const uint32_t*)(pl);
                al[mt][1] = *(const uint32_t*)(pl + 8 * GM_RS);
                al[mt][2] = *(const uint32_t*)(pl + 16);
                al[mt][3] = *(const uint32_t*)(pl + 8 * GM_RS + 16);
            }
#pragma unroll
            for (int nt = 0; nt < 4; nt++) {
                int rowb = wn * 32 + nt * 8 + fr;
                const char* pb = sBh + rowb * GM_RS + (kk + fq) * 2;
                const char* pl = sBl + rowb * GM_RS + (kk + fq) * 2;
                bh[nt][0] = *(const uint32_t*)(pb);
                bh[nt][1] = *(const uint32_t*)(pb + 16);
                bl[nt][0] = *(const uint32_t*)(pl);
                bl[nt][1] = *(const uint32_t*)(pl + 16);
            }
#pragma unroll
            for (int mt = 0; mt < 4; mt++)
#pragma unroll
                for (int nt = 0; nt < 4; nt++) {
                    mma16816(acc[mt][nt], ah[mt], bh[nt]);
                    mma16816(acc[mt][nt], ah[mt], bl[nt]);
                    mma16816(acc[mt][nt], al[mt], bh[nt]);
                }
        }
        __syncthreads();
    }

    // Epilogue: each thread owns (row fr, fr+8) x (cols fq, fq+1) per tile
#pragma unroll
    for (int mt = 0; mt < 4; mt++) {
#pragma unroll
        for (int nt = 0; nt < 4; nt++) {
            long m = m0 + wm * 64 + mt * 16 + fr;
            int  n = (int)n0 + wn * 32 + nt * 8 + fq;
            float* d0;
            float* d1;
            if (mode == 0) {
                d0 = C + m * DMODEL + n;
                d1 = d0 + 8 * DMODEL;
            } else {
                int b = (int)(m >> 11), s = (int)(m & 2047);
                int h = n >> 7, dh = n & 127;
                long base = ((long)(b * NHEADS + h) * TTOT + CACHE + s) * HEADDIM + dh;
                d0 = C + base;
                d1 = C + base + 8 * HEADDIM;
            }
            *(float2*)d0 = make_float2(acc[mt][nt][0], acc[mt][nt][1]);
            *(float2*)d1 = make_float2(acc[mt][nt][2], acc[mt][nt][3]);
        }
    }
}

// ---------------------------------------------------------------------------
// Flash attention (fp32 SIMT) — unchanged from passing R3 version.
// ---------------------------------------------------------------------------
#define AT_STRIDE 132
#define AT_SMEM_FLOATS (128*AT_STRIDE + 128*AT_STRIDE + 128*AT_STRIDE + 2*128)
#define AT_SMEM_BYTES (AT_SMEM_FLOATS * 4)

__global__ __launch_bounds__(256) void attn_kernel(
    const float* __restrict__ Q, const float* __restrict__ Kc,
    const float* __restrict__ Vc, float* __restrict__ Oa)
{
    extern __shared__ float sm[];
    float* Qt   = sm;
    float* KV   = Qt + 128 * AT_STRIDE;
    float* Ss   = KV + 128 * AT_STRIDE;
    float* mrow = Ss + 128 * AT_STRIDE;
    float* lrow = mrow + 128;

    const int bh = blockIdx.y;
    const int b  = bh >> 4;
    const int h  = bh & 15;
    const int s0 = blockIdx.x * 128;
    const int tid = threadIdx.x;
    const int tx = tid & 15;
    const int ty = tid >> 4;

    const float scale = 0.08838834764831845f;

    const float* qbase = Q + ((long)b * SEQ + s0) * DMODEL + h * HEADDIM;
    for (int i = tid; i < 128 * 32; i += 256) {
        int c4 = i >> 7;
        int m  = i & 127;
        float4 v = *(const float4*)(qbase + (long)m * DMODEL + c4 * 4);
        Qt[(c4 * 4 + 0) * AT_STRIDE + m] = v.x;
        Qt[(c4 * 4 + 1) * AT_STRIDE + m] = v.y;
        Qt[(c4 * 4 + 2) * AT_STRIDE + m] = v.z;
        Qt[(c4 * 4 + 3) * AT_STRIDE + m] = v.w;
    }
    if (tid < 128) { mrow[tid] = -INFINITY; lrow[tid] = 0.f; }

    float o_acc[8][8];
#pragma unroll
    for (int i = 0; i < 8; i++)
#pragma unroll
        for (int j = 0; j < 8; j++) o_acc[i][j] = 0.f;

    const float* kbase = Kc + (long)bh * TTOT * HEADDIM;
    const float* vbase = Vc + (long)bh * TTOT * HEADDIM;

    for (int t0 = 0; t0 < TTOT; t0 += 128) {
        __syncthreads();
        for (int i = tid; i < 128 * 32; i += 256) {
            int c4 = i >> 7;
            int t  = i & 127;
            float4 v = *(const float4*)(kbase + (long)(t0 + t) * HEADDIM + c4 * 4);
            KV[(c4 * 4 + 0) * AT_STRIDE + t] = v.x;
            KV[(c4 * 4 + 1) * AT_STRIDE + t] = v.y;
            KV[(c4 * 4 + 2) * AT_STRIDE + t] = v.z;
            KV[(c4 * 4 + 3) * AT_STRIDE + t] = v.w;
        }
        __syncthreads();

        float s_acc[8][8];
#pragma unroll
        for (int i = 0; i < 8; i++)
#pragma unroll
            for (int j = 0; j < 8; j++) s_acc[i][j] = 0.f;

        for (int d = 0; d < 128; d++) {
            float af[8], bf[8];
            *(float4*)&af[0] = *(float4*)(Qt + d * AT_STRIDE + ty * 8);
            *(float4*)&af[4] = *(float4*)(Qt + d * AT_STRIDE + ty * 8 + 4);
            *(float4*)&bf[0] = *(float4*)(KV + d * AT_STRIDE + tx * 8);
            *(float4*)&bf[4] = *(float4*)(KV + d * AT_STRIDE + tx * 8 + 4);
#pragma unroll
            for (int i = 0; i < 8; i++)
#pragma unroll
                for (int j = 0; j < 8; j++)
                    s_acc[i][j] = fmaf(af[i], bf[j], s_acc[i][j]);
        }
#pragma unroll
        for (int i = 0; i < 8; i++)
#pragma unroll
            for (int j = 0; j < 8; j++) s_acc[i][j] *= scale;

        __syncthreads();

        for (int i = tid; i < 128 * 32; i += 256) {
            int t  = i >> 5;
            int c4 = i & 31;
            float4 v = *(const float4*)(vbase + (long)(t0 + t) * HEADDIM + c4 * 4);
            *(float4*)(KV + t * 128 + c4 * 4) = v;
        }

        float alpha[8];
#pragma unroll
        for (int i = 0; i < 8; i++) {
            float mx = s_acc[i][0];
#pragma unroll
            for (int j = 1; j < 8; j++) mx = fmaxf(mx, s_acc[i][j]);
#pragma unroll
            for (int off = 8; off; off >>= 1)
                mx = fmaxf(mx, __shfl_xor_sync(0xffffffffu, mx, off));
            int r = ty * 8 + i;
            float m_old = mrow[r];
            float m_new = fmaxf(m_old, mx);
            alpha[i] = __expf(m_old - m_new);
            float sum = 0.f;
#pragma unroll
            for (int j = 0; j < 8; j++) {
                float e = __expf(s_acc[i][j] - m_new);
                s_acc[i][j] = e;
                sum += e;
            }
#pragma unroll
            for (int off = 8; off; off >>= 1)
                sum += __shfl_xor_sync(0xffffffffu, sum, off);
            if (tx == 0) {
                lrow[r] = lrow[r] * alpha[i] + sum;
                mrow[r] = m_new;
            }
            *(float4*)(Ss + r * AT_STRIDE + tx * 8) =
                make_float4(s_acc[i][0], s_acc[i][1], s_acc[i][2], s_acc[i][3]);
            *(float4*)(Ss + r * AT_STRIDE + tx * 8 + 4) =
                make_float4(s_acc[i][4], s_acc[i][5], s_acc[i][6], s_acc[i][7]);
        }
        __syncthreads();

#pragma unroll
        for (int i = 0; i < 8; i++)
#pragma unroll
            for (int j = 0; j < 8; j++) o_acc[i][j] *= alpha[i];

        for (int t = 0; t < 128; t++) {
            float vf[8];
            *(float4*)&vf[0] = *(float4*)(KV + t * 128 + tx * 8);
            *(float4*)&vf[4] = *(float4*)(KV + t * 128 + tx * 8 + 4);
#pragma unroll
            for (int i = 0; i < 8; i++) {
                float p = Ss[(ty * 8 + i) * AT_STRIDE + t];
#pragma unroll
                for (int j = 0; j < 8; j++)
                    o_acc[i][j] = fmaf(p, vf[j], o_acc[i][j]);
            }
        }
    }

#pragma unroll
    for (int i = 0; i < 8; i++) {
        int r = ty * 8 + i;
        float inv = 1.f / lrow[r];
        float* p = Oa + ((long)b * SEQ + s0 + r) * DMODEL + h * HEADDIM + tx * 8;
        ((float4*)p)[0] = make_float4(o_acc[i][0]*inv, o_acc[i][1]*inv,
                                      o_acc[i][2]*inv, o_acc[i][3]*inv);
        ((float4*)p)[1] = make_float4(o_acc[i][4]*inv, o_acc[i][5]*inv,
                                      o_acc[i][6]*inv, o_acc[i][7]*inv);
    }
}

// ---------------------------------------------------------------------------
// kernel_launch
// Inputs: x, cached_k, cached_v, W_q, W_k, W_v, W_o
// Output: [ out (B,S,D) | k (B,H,TTOT,Dh) | v (B,H,TTOT,Dh) ]
// ---------------------------------------------------------------------------
extern "C" void kernel_launch(void* const* d_in, const int* in_sizes, int n_in,
                              void* d_out, int out_size)
{
    const float* x  = (const float*)d_in[0];
    const float* ck = (const float*)d_in[1];
    const float* cv = (const float*)d_in[2];
    const float* wts[4] = { (const float*)d_in[3], (const float*)d_in[4],
                            (const float*)d_in[5], (const float*)d_in[6] };

    float* out   = (float*)d_out;
    float* k_out = out + (long)MROWS * DMODEL;
    float* v_out = k_out + (long)BATCH * NHEADS * TTOT * HEADDIM;

    float* qs;  cudaGetSymbolAddress((void**)&qs, g_q);
    float* at;  cudaGetSymbolAddress((void**)&at, g_attn);
    __nv_bfloat16* ah; cudaGetSymbolAddress((void**)&ah, g_ah);
    __nv_bfloat16* al; cudaGetSymbolAddress((void**)&al, g_al);
    __nv_bfloat16* wh; cudaGetSymbolAddress((void**)&wh, g_wh);
    __nv_bfloat16* wl; cudaGetSymbolAddress((void**)&wl, g_wl);

    // 1) copy KV cache into outputs
    {
        const int N4 = BATCH * NHEADS * CACHE * HEADDIM / 4;
        copy_cache_kernel<<<(N4 + 255) / 256, 256>>>(
            (const float4*)ck, (const float4*)cv, (float4*)k_out, (float4*)v_out);
    }

    // 2) hi/lo splits: x and the 4 weights
    {
        const int xn4 = MROWS * DMODEL / 4;
        split_kernel<<<xn4 / 256, 256>>>((const float4*)x, ah, al, xn4);
        const int wn4 = DMODEL * DMODEL / 4;
        for (int i = 0; i < 4; i++)
            split_kernel<<<wn4 / 256, 256>>>((const float4*)wts[i],
                                             wh + (long)i * DMODEL * DMODEL,
                                             wl + (long)i * DMODEL * DMODEL, wn4);
    }

    // 3) Q, K, V projections on tensor cores (HMMA)
    cudaFuncSetAttribute(gemm_tc_kernel, cudaFuncAttributeMaxDynamicSharedMemorySize,
                         GM_SMEM);
    dim3 gg(DMODEL / 128, MROWS / 128);  // (16, 32)
    const long WSZ = (long)DMODEL * DMODEL;
    gemm_tc_kernel<<<gg, 256, GM_SMEM>>>(ah, al, wh + 0 * WSZ, wl + 0 * WSZ, qs,    0);
    gemm_tc_kernel<<<gg, 256, GM_SMEM>>>(ah, al, wh + 1 * WSZ, wl + 1 * WSZ, k_out, 1);
    gemm_tc_kernel<<<gg, 256, GM_SMEM>>>(ah, al, wh + 2 * WSZ, wl + 2 * WSZ, v_out, 1);

    // 4) attention (fp32 SIMT)
    cudaFuncSetAttribute(attn_kernel, cudaFuncAttributeMaxDynamicSharedMemorySize,
                         AT_SMEM_BYTES);
    attn_kernel<<<dim3(SEQ / 128, BATCH * NHEADS), 256, AT_SMEM_BYTES>>>(
        qs, k_out, v_out, at);

    // 5) split attention output, then O projection on tensor cores
    {
        const int xn4 = MROWS * DMODEL / 4;
        split_kernel<<<xn4 / 256, 256>>>((const float4*)at, ah, al, xn4);
    }
    gemm_tc_kernel<<<gg, 256, GM_SMEM>>>(ah, al, wh + 3 * WSZ, wl + 3 * WSZ, out, 0);
}

// round 7
// speedup vs baseline: 3.5681x; 2.2107x over previous
#include <cuda_runtime.h>
#include <cuda_bf16.h>
#include <math.h>
#include <stdint.h>

// Problem constants
#define BATCH 2
#define SEQ 2048
#define DMODEL 2048
#define NHEADS 16
#define HEADDIM 128
#define CACHE 2048
#define TTOT 4096           // CACHE + SEQ
#define MROWS (BATCH*SEQ)   // 4096
#define KVELEMS (BATCH*NHEADS*TTOT*HEADDIM)  // 16777216

// ---------------------------------------------------------------------------
// Scratch (device globals; no allocations allowed)
// ---------------------------------------------------------------------------
__device__ float g_q[MROWS * DMODEL];
__device__ float g_attn[MROWS * DMODEL];
__device__ __nv_bfloat16 g_ah[MROWS * DMODEL];   // activation hi (x / q / attn-out)
__device__ __nv_bfloat16 g_al[MROWS * DMODEL];   // activation lo
__device__ __nv_bfloat16 g_wh[4][DMODEL * DMODEL];
__device__ __nv_bfloat16 g_wl[4][DMODEL * DMODEL];
__device__ __nv_bfloat16 g_kh[KVELEMS];
__device__ __nv_bfloat16 g_kl[KVELEMS];
__device__ __nv_bfloat16 g_vh[KVELEMS];
__device__ __nv_bfloat16 g_vl[KVELEMS];

// ---------------------------------------------------------------------------
// Helpers
// ---------------------------------------------------------------------------
__device__ __forceinline__ uint32_t smem_u32(const void* p) {
    uint32_t a;
    asm("{ .reg .u64 t; cvta.to.shared.u64 t, %1; cvt.u32.u64 %0, t; }" : "=r"(a) : "l"(p));
    return a;
}
__device__ __forceinline__ void cp16(void* dst_smem, const void* src) {
    uint32_t d = smem_u32(dst_smem);
    asm volatile("cp.async.cg.shared.global [%0], [%1], 16;" :: "r"(d), "l"(src) : "memory");
}
__device__ __forceinline__ void cp_commit() {
    asm volatile("cp.async.commit_group;" ::: "memory");
}
__device__ __forceinline__ void cp_wait1() {
    asm volatile("cp.async.wait_group 1;" ::: "memory");
}
__device__ __forceinline__ void cp_wait0() {
    asm volatile("cp.async.wait_group 0;" ::: "memory");
}
// D += A*B : m16n8k16 bf16, fp32 accum
__device__ __forceinline__ void mma16816(float* c, const uint32_t* a, const uint32_t* b) {
    asm volatile(
        "mma.sync.aligned.m16n8k16.row.col.f32.bf16.bf16.f32 "
        "{%0,%1,%2,%3}, {%4,%5,%6,%7}, {%8,%9}, {%0,%1,%2,%3};"
        : "+f"(c[0]), "+f"(c[1]), "+f"(c[2]), "+f"(c[3])
        : "r"(a[0]), "r"(a[1]), "r"(a[2]), "r"(a[3]), "r"(b[0]), "r"(b[1]));
}
__device__ __forceinline__ void ldsm_x2_trans(uint32_t& r0, uint32_t& r1, uint32_t saddr) {
    asm volatile("ldmatrix.sync.aligned.m8n8.x2.trans.shared.b16 {%0,%1}, [%2];"
                 : "=r"(r0), "=r"(r1) : "r"(saddr));
}
// pack pair of floats to bf16x2 hi and residual lo
__device__ __forceinline__ void packsplit(float p0, float p1, uint32_t& hi, uint32_t& lo) {
    __nv_bfloat162 h = __floats2bfloat162_rn(p0, p1);   // .x=p0 (low), .y=p1 (high)
    float f0 = __low2float(h), f1 = __high2float(h);
    __nv_bfloat162 g = __floats2bfloat162_rn(p0 - f0, p1 - f1);
    hi = *(uint32_t*)&h;
    lo = *(uint32_t*)&g;
}

// ---------------------------------------------------------------------------
// fp32 -> bf16 hi/lo split
// ---------------------------------------------------------------------------
__global__ __launch_bounds__(256) void split_kernel(
    const float4* __restrict__ in, __nv_bfloat16* __restrict__ hi,
    __nv_bfloat16* __restrict__ lo, int n4)
{
    int i = blockIdx.x * blockDim.x + threadIdx.x;
    if (i >= n4) return;
    float4 v = in[i];
    union { __nv_bfloat16 h[4]; uint2 u; } H, L;
    float f[4] = {v.x, v.y, v.z, v.w};
#pragma unroll
    for (int j = 0; j < 4; j++) {
        __nv_bfloat16 h = __float2bfloat16_rn(f[j]);
        H.h[j] = h;
        L.h[j] = __float2bfloat16_rn(f[j] - __bfloat162float(h));
    }
    *(uint2*)(hi + (long)i * 4) = H.u;
    *(uint2*)(lo + (long)i * 4) = L.u;
}

// ---------------------------------------------------------------------------
// Cache copy: cached_k/v -> k_out/v_out rows [0,CACHE)
// ---------------------------------------------------------------------------
__global__ __launch_bounds__(256) void copy_cache_kernel(
    const float4* __restrict__ ck, const float4* __restrict__ cv,
    float4* __restrict__ ko, float4* __restrict__ vo)
{
    int i = blockIdx.x * blockDim.x + threadIdx.x;
    const int N4 = BATCH * NHEADS * CACHE * HEADDIM / 4;
    if (i >= N4) return;
    const int per_bh = CACHE * HEADDIM / 4;
    int bh  = i / per_bh;
    int rem = i - bh * per_bh;
    long dst = (long)bh * (TTOT * HEADDIM / 4) + rem;
    ko[dst] = ck[i];
    vo[dst] = cv[i];
}

// ---------------------------------------------------------------------------
// HMMA GEMM (unchanged from passing R6): C[m,n] = sum_k A[m,k]*B[n,k]
// ---------------------------------------------------------------------------
#define GM_RS    80
#define GM_MAT   (128 * GM_RS)
#define GM_BUF   (4 * GM_MAT)
#define GM_SMEM  (2 * GM_BUF)
#define GM_KCH   64

__device__ __forceinline__ void gm_issue_chunk(
    char* buf, const __nv_bfloat16* Ah, const __nv_bfloat16* Al,
    const __nv_bfloat16* Bh, const __nv_bfloat16* Bl,
    long m0, long n0, int k0, int tid)
{
    const int row = tid >> 2;
    const int seg = tid & 3;
#pragma unroll
    for (int it = 0; it < 2; it++) {
        int rr = row + it * 64;
        long off = (long)k0 + seg * 8;
        cp16(buf + 0 * GM_MAT + rr * GM_RS + seg * 16, Ah + (m0 + rr) * DMODEL + off);
        cp16(buf + 1 * GM_MAT + rr * GM_RS + seg * 16, Al + (m0 + rr) * DMODEL + off);
        cp16(buf + 2 * GM_MAT + rr * GM_RS + seg * 16, Bh + (n0 + rr) * DMODEL + off);
        cp16(buf + 3 * GM_MAT + rr * GM_RS + seg * 16, Bl + (n0 + rr) * DMODEL + off);
    }
    cp_commit();
}

__global__ __launch_bounds__(256, 1)
void gemm_tc_kernel(const __nv_bfloat16* __restrict__ Ah,
                    const __nv_bfloat16* __restrict__ Al,
                    const __nv_bfloat16* __restrict__ Bh,
                    const __nv_bfloat16* __restrict__ Bl,
                    float* __restrict__ C, int mode)
{
    extern __shared__ char dsm[];
    const int tid  = threadIdx.x;
    const int wid  = tid >> 5;
    const int lane = tid & 31;
    const int wm   = wid >> 2;
    const int wn   = wid & 3;
    const long m0 = (long)blockIdx.y * 128;
    const long n0 = (long)blockIdx.x * 128;

    const int fr = lane >> 2;
    const int fq = (lane & 3) * 2;

    float acc[4][4][4];
#pragma unroll
    for (int i = 0; i < 4; i++)
#pragma unroll
        for (int j = 0; j < 4; j++)
#pragma unroll
            for (int t = 0; t < 4; t++) acc[i][j][t] = 0.f;

    gm_issue_chunk(dsm, Ah, Al, Bh, Bl, m0, n0, 0, tid);

    for (int c = 0; c < GM_KCH; c++) {
        if (c + 1 < GM_KCH)
            gm_issue_chunk(dsm + ((c + 1) & 1) * GM_BUF, Ah, Al, Bh, Bl,
                           m0, n0, (c + 1) * 32, tid);
        if (c + 1 < GM_KCH) cp_wait1(); else cp_wait0();
        __syncthreads();

        const char* sb  = dsm + (c & 1) * GM_BUF;
        const char* sAh = sb;
        const char* sAl = sb + GM_MAT;
        const char* sBh = sb + 2 * GM_MAT;
        const char* sBl = sb + 3 * GM_MAT;

#pragma unroll
        for (int kk = 0; kk < 32; kk += 16) {
            uint32_t ah[4][4], al[4][4], bh[4][2], bl[4][2];
#pragma unroll
            for (int mt = 0; mt < 4; mt++) {
                int row0 = wm * 64 + mt * 16 + fr;
                const char* pa = sAh + row0 * GM_RS + (kk + fq) * 2;
                const char* pl = sAl + row0 * GM_RS + (kk + fq) * 2;
                ah[mt][0] = *(const uint32_t*)(pa);
                ah[mt][1] = *(const uint32_t*)(pa + 8 * GM_RS);
                ah[mt][2] = *(const uint32_t*)(pa + 16);
                ah[mt][3] = *(const uint32_t*)(pa + 8 * GM_RS + 16);
                al[mt][0] = *(const uint32_t*)(pl);
                al[mt][1] = *(const uint32_t*)(pl + 8 * GM_RS);
                al[mt][2] = *(const uint32_t*)(pl + 16);
                al[mt][3] = *(const uint32_t*)(pl + 8 * GM_RS + 16);
            }
#pragma unroll
            for (int nt = 0; nt < 4; nt++) {
                int rowb = wn * 32 + nt * 8 + fr;
                const char* pb = sBh + rowb * GM_RS + (kk + fq) * 2;
                const char* pl = sBl + rowb * GM_RS + (kk + fq) * 2;
                bh[nt][0] = *(const uint32_t*)(pb);
                bh[nt][1] = *(const uint32_t*)(pb + 16);
                bl[nt][0] = *(const uint32_t*)(pl);
                bl[nt][1] = *(const uint32_t*)(pl + 16);
            }
#pragma unroll
            for (int mt = 0; mt < 4; mt++)
#pragma unroll
                for (int nt = 0; nt < 4; nt++) {
                    mma16816(acc[mt][nt], ah[mt], bh[nt]);
                    mma16816(acc[mt][nt], ah[mt], bl[nt]);
                    mma16816(acc[mt][nt], al[mt], bh[nt]);
                }
        }
        __syncthreads();
    }

#pragma unroll
    for (int mt = 0; mt < 4; mt++) {
#pragma unroll
        for (int nt = 0; nt < 4; nt++) {
            long m = m0 + wm * 64 + mt * 16 + fr;
            int  n = (int)n0 + wn * 32 + nt * 8 + fq;
            float* d0;
            float* d1;
            if (mode == 0) {
                d0 = C + m * DMODEL + n;
                d1 = d0 + 8 * DMODEL;
            } else {
                int b = (int)(m >> 11), s = (int)(m & 2047);
                int h = n >> 7, dh = n & 127;
                long base = ((long)(b * NHEADS + h) * TTOT + CACHE + s) * HEADDIM + dh;
                d0 = C + base;
                d1 = C + base + 8 * HEADDIM;
            }
            *(float2*)d0 = make_float2(acc[mt][nt][0], acc[mt][nt][1]);
            *(float2*)d1 = make_float2(acc[mt][nt][2], acc[mt][nt][3]);
        }
    }
}

// ---------------------------------------------------------------------------
// Flash attention on HMMA (bf16 hi/lo, fp32 accum).
// CTA: one (b,h) and 128 query rows. 8 warps x 16 rows. BT=64 keys/iter.
// S: 3 MMAs (QhKh+QhKl+QlKh). P split in registers; PV: 3 MMAs (PhVh+PhVl+PlVh).
// K/V tiles double-buffered via cp.async; Q resident in smem.
// ---------------------------------------------------------------------------
#define AT_RS    272                 // row stride bytes (128 bf16 + 16B pad)
#define AT_QL    34816               // 128*272
#define AT_STG0  69632
#define AT_STGSZ 69632               // 4 mats * 64 * 272
#define AT_KL    17408
#define AT_VH    34816
#define AT_VL    52224
#define AT_SMEM  208896
#define AT_NIT   (TTOT / 64)         // 64

__device__ __forceinline__ void at_issue_kv(
    char* dsm, const __nv_bfloat16* Kh, const __nv_bfloat16* Kl,
    const __nv_bfloat16* Vh, const __nv_bfloat16* Vl,
    long kvoff, int it, int tid)
{
    char* stg = dsm + AT_STG0 + (it & 1) * AT_STGSZ;
    const int t0 = it * 64;
#pragma unroll
    for (int i = 0; i < 16; i++) {
        int idx = tid + i * 256;         // 0..4095
        int mat = idx >> 10;             // 0..3
        int row = (idx >> 4) & 63;
        int ch  = idx & 15;
        const __nv_bfloat16* src;
        if      (mat == 0) src = Kh;
        else if (mat == 1) src = Kl;
        else if (mat == 2) src = Vh;
        else               src = Vl;
        cp16(stg + mat * 17408 + row * AT_RS + ch * 16,
             src + kvoff + (long)(t0 + row) * HEADDIM + ch * 8);
    }
    cp_commit();
}

__global__ __launch_bounds__(256, 1) void attn_kernel(
    const __nv_bfloat16* __restrict__ Qh, const __nv_bfloat16* __restrict__ Ql,
    const __nv_bfloat16* __restrict__ Kh, const __nv_bfloat16* __restrict__ Kl,
    const __nv_bfloat16* __restrict__ Vh, const __nv_bfloat16* __restrict__ Vl,
    float* __restrict__ Oa)
{
    extern __shared__ char dsm[];
    const int tid = threadIdx.x;
    const int w  = tid >> 5;
    const int l  = tid & 31;
    const int fr = l >> 2;              // fragment row 0..7
    const int fcb = (l & 3) * 4;        // fragment col byte offset (2 bf16)
    const int bh = blockIdx.y;
    const int b  = bh >> 4, h = bh & 15;
    const int s0 = blockIdx.x * 128;
    const uint32_t sbase = smem_u32(dsm);
    const float scale = 0.08838834764831845f;   // 1/sqrt(128)

    // Issue Q tiles (hi+lo), grouped with KV stage 0
    {
        const long qoff = ((long)b * SEQ + s0) * DMODEL + h * HEADDIM;
#pragma unroll
        for (int i = 0; i < 16; i++) {
            int idx = tid + i * 256;     // 0..4095
            int mat = idx >> 11;         // 0..1
            int row = (idx >> 4) & 127;
            int ch  = idx & 15;
            const __nv_bfloat16* src = (mat ? Ql : Qh) + qoff + (long)row * DMODEL + ch * 8;
            cp16(dsm + mat * AT_QL + row * AT_RS + ch * 16, src);
        }
    }
    const long kvoff = (long)bh * TTOT * HEADDIM;
    at_issue_kv(dsm, Kh, Kl, Vh, Vl, kvoff, 0, tid);   // commits (Q + KV0)
    at_issue_kv(dsm, Kh, Kl, Vh, Vl, kvoff, 1, tid);

    float m_lo = -INFINITY, m_hi = -INFINITY, l_lo = 0.f, l_hi = 0.f;
    float oacc[16][4];
#pragma unroll
    for (int i = 0; i < 16; i++)
#pragma unroll
        for (int j = 0; j < 4; j++) oacc[i][j] = 0.f;

    for (int it = 0; it < AT_NIT; it++) {
        if (it + 1 < AT_NIT) cp_wait1(); else cp_wait0();
        __syncthreads();

        const char* stg = dsm + AT_STG0 + (it & 1) * AT_STGSZ;

        // ---- S = Q K^T ----
        float sacc[8][4];
#pragma unroll
        for (int i = 0; i < 8; i++)
#pragma unroll
            for (int j = 0; j < 4; j++) sacc[i][j] = 0.f;

        const char* qa0 = dsm + (w * 16 + fr) * AT_RS + fcb;
        const char* kb0 = stg + fr * AT_RS + fcb;
#pragma unroll
        for (int ks = 0; ks < 8; ks++) {
            uint32_t aH[4], aL[4];
            const char* qa = qa0 + ks * 32;
            aH[0] = *(const uint32_t*)(qa);
            aH[1] = *(const uint32_t*)(qa + 8 * AT_RS);
            aH[2] = *(const uint32_t*)(qa + 16);
            aH[3] = *(const uint32_t*)(qa + 8 * AT_RS + 16);
            const char* qb = qa + AT_QL;
            aL[0] = *(const uint32_t*)(qb);
            aL[1] = *(const uint32_t*)(qb + 8 * AT_RS);
            aL[2] = *(const uint32_t*)(qb + 16);
            aL[3] = *(const uint32_t*)(qb + 8 * AT_RS + 16);
#pragma unroll
            for (int nt = 0; nt < 8; nt++) {
                const char* kb = kb0 + nt * 8 * AT_RS + ks * 32;
                uint32_t bH[2] = { *(const uint32_t*)(kb), *(const uint32_t*)(kb + 16) };
                uint32_t bL[2] = { *(const uint32_t*)(kb + AT_KL), *(const uint32_t*)(kb + AT_KL + 16) };
                mma16816(sacc[nt], aH, bH);
                mma16816(sacc[nt], aH, bL);
                mma16816(sacc[nt], aL, bH);
            }
        }

        // ---- online softmax (rows fr and fr+8 of this warp) ----
        float mx0 = -INFINITY, mx1 = -INFINITY;
#pragma unroll
        for (int nt = 0; nt < 8; nt++) {
#pragma unroll
            for (int j = 0; j < 4; j++) sacc[nt][j] *= scale;
            mx0 = fmaxf(mx0, fmaxf(sacc[nt][0], sacc[nt][1]));
            mx1 = fmaxf(mx1, fmaxf(sacc[nt][2], sacc[nt][3]));
        }
        mx0 = fmaxf(mx0, __shfl_xor_sync(0xffffffffu, mx0, 1));
        mx0 = fmaxf(mx0, __shfl_xor_sync(0xffffffffu, mx0, 2));
        mx1 = fmaxf(mx1, __shfl_xor_sync(0xffffffffu, mx1, 1));
        mx1 = fmaxf(mx1, __shfl_xor_sync(0xffffffffu, mx1, 2));
        float mn0 = fmaxf(m_lo, mx0), mn1 = fmaxf(m_hi, mx1);
        float al0 = __expf(m_lo - mn0), al1 = __expf(m_hi - mn1);
        float sm0 = 0.f, sm1 = 0.f;
#pragma unroll
        for (int nt = 0; nt < 8; nt++) {
            sacc[nt][0] = __expf(sacc[nt][0] - mn0);
            sacc[nt][1] = __expf(sacc[nt][1] - mn0);
            sacc[nt][2] = __expf(sacc[nt][2] - mn1);
            sacc[nt][3] = __expf(sacc[nt][3] - mn1);
            sm0 += sacc[nt][0] + sacc[nt][1];
            sm1 += sacc[nt][2] + sacc[nt][3];
        }
        sm0 += __shfl_xor_sync(0xffffffffu, sm0, 1);
        sm0 += __shfl_xor_sync(0xffffffffu, sm0, 2);
        sm1 += __shfl_xor_sync(0xffffffffu, sm1, 1);
        sm1 += __shfl_xor_sync(0xffffffffu, sm1, 2);
        l_lo = l_lo * al0 + sm0;  m_lo = mn0;
        l_hi = l_hi * al1 + sm1;  m_hi = mn1;

#pragma unroll
        for (int dt = 0; dt < 16; dt++) {
            oacc[dt][0] *= al0;  oacc[dt][1] *= al0;
            oacc[dt][2] *= al1;  oacc[dt][3] *= al1;
        }

        // ---- O += P V ----
        const uint32_t vbase = sbase + AT_STG0 + (uint32_t)((it & 1) * AT_STGSZ) + AT_VH;
#pragma unroll
        for (int kt = 0; kt < 4; kt++) {
            uint32_t aPh[4], aPl[4];
            packsplit(sacc[2 * kt][0],     sacc[2 * kt][1],     aPh[0], aPl[0]);
            packsplit(sacc[2 * kt][2],     sacc[2 * kt][3],     aPh[1], aPl[1]);
            packsplit(sacc[2 * kt + 1][0], sacc[2 * kt + 1][1], aPh[2], aPl[2]);
            packsplit(sacc[2 * kt + 1][2], sacc[2 * kt + 1][3], aPh[3], aPl[3]);
            uint32_t vrow = vbase + (uint32_t)((kt * 16 + (l & 15)) * AT_RS);
#pragma unroll
            for (int dt = 0; dt < 16; dt++) {
                uint32_t bvh[2], bvl[2];
                ldsm_x2_trans(bvh[0], bvh[1], vrow + dt * 16);
                ldsm_x2_trans(bvl[0], bvl[1], vrow + AT_KL + dt * 16);
                mma16816(oacc[dt], aPh, bvh);
                mma16816(oacc[dt], aPh, bvl);
                mma16816(oacc[dt], aPl, bvh);
            }
        }

        __syncthreads();
        if (it + 2 < AT_NIT)
            at_issue_kv(dsm, Kh, Kl, Vh, Vl, kvoff, it + 2, tid);
    }

    // ---- epilogue: normalize + store to (B,S,DMODEL) head-interleaved ----
    float inv0 = 1.f / l_lo, inv1 = 1.f / l_hi;
    long r0 = ((long)b * SEQ + s0 + w * 16 + fr) * DMODEL + h * HEADDIM + (l & 3) * 2;
#pragma unroll
    for (int dt = 0; dt < 16; dt++) {
        *(float2*)(Oa + r0 + dt * 8) =
            make_float2(oacc[dt][0] * inv0, oacc[dt][1] * inv0);
        *(float2*)(Oa + r0 + 8 * DMODEL + dt * 8) =
            make_float2(oacc[dt][2] * inv1, oacc[dt][3] * inv1);
    }
}

// ---------------------------------------------------------------------------
// kernel_launch
// Inputs: x, cached_k, cached_v, W_q, W_k, W_v, W_o
// Output: [ out (B,S,D) | k (B,H,TTOT,Dh) | v (B,H,TTOT,Dh) ]
// ---------------------------------------------------------------------------
extern "C" void kernel_launch(void* const* d_in, const int* in_sizes, int n_in,
                              void* d_out, int out_size)
{
    const float* x  = (const float*)d_in[0];
    const float* ck = (const float*)d_in[1];
    const float* cv = (const float*)d_in[2];
    const float* wts[4] = { (const float*)d_in[3], (const float*)d_in[4],
                            (const float*)d_in[5], (const float*)d_in[6] };

    float* out   = (float*)d_out;
    float* k_out = out + (long)MROWS * DMODEL;
    float* v_out = k_out + (long)KVELEMS;

    float* qs;  cudaGetSymbolAddress((void**)&qs, g_q);
    float* at;  cudaGetSymbolAddress((void**)&at, g_attn);
    __nv_bfloat16 *ah, *al, *wh, *wl, *kh, *kl, *vh, *vl;
    cudaGetSymbolAddress((void**)&ah, g_ah);
    cudaGetSymbolAddress((void**)&al, g_al);
    cudaGetSymbolAddress((void**)&wh, g_wh);
    cudaGetSymbolAddress((void**)&wl, g_wl);
    cudaGetSymbolAddress((void**)&kh, g_kh);
    cudaGetSymbolAddress((void**)&kl, g_kl);
    cudaGetSymbolAddress((void**)&vh, g_vh);
    cudaGetSymbolAddress((void**)&vl, g_vl);

    // 1) copy KV cache into outputs
    {
        const int N4 = BATCH * NHEADS * CACHE * HEADDIM / 4;
        copy_cache_kernel<<<(N4 + 255) / 256, 256>>>(
            (const float4*)ck, (const float4*)cv, (float4*)k_out, (float4*)v_out);
    }

    // 2) hi/lo splits: x and the 4 weights
    {
        const int xn4 = MROWS * DMODEL / 4;
        split_kernel<<<xn4 / 256, 256>>>((const float4*)x, ah, al, xn4);
        const int wn4 = DMODEL * DMODEL / 4;
        for (int i = 0; i < 4; i++)
            split_kernel<<<wn4 / 256, 256>>>((const float4*)wts[i],
                                             wh + (long)i * DMODEL * DMODEL,
                                             wl + (long)i * DMODEL * DMODEL, wn4);
    }

    // 3) Q, K, V projections on tensor cores (HMMA)
    cudaFuncSetAttribute(gemm_tc_kernel, cudaFuncAttributeMaxDynamicSharedMemorySize,
                         GM_SMEM);
    dim3 gg(DMODEL / 128, MROWS / 128);  // (16, 32)
    const long WSZ = (long)DMODEL * DMODEL;
    gemm_tc_kernel<<<gg, 256, GM_SMEM>>>(ah, al, wh + 0 * WSZ, wl + 0 * WSZ, qs,    0);
    gemm_tc_kernel<<<gg, 256, GM_SMEM>>>(ah, al, wh + 1 * WSZ, wl + 1 * WSZ, k_out, 1);
    gemm_tc_kernel<<<gg, 256, GM_SMEM>>>(ah, al, wh + 2 * WSZ, wl + 2 * WSZ, v_out, 1);

    // 4) hi/lo splits for attention operands: q (reuse ah/al), k, v
    {
        const int qn4 = MROWS * DMODEL / 4;
        split_kernel<<<qn4 / 256, 256>>>((const float4*)qs, ah, al, qn4);
        const int kn4 = KVELEMS / 4;
        split_kernel<<<kn4 / 256, 256>>>((const float4*)k_out, kh, kl, kn4);
        split_kernel<<<kn4 / 256, 256>>>((const float4*)v_out, vh, vl, kn4);
    }

    // 5) attention on tensor cores
    cudaFuncSetAttribute(attn_kernel, cudaFuncAttributeMaxDynamicSharedMemorySize,
                         AT_SMEM);
    attn_kernel<<<dim3(SEQ / 128, BATCH * NHEADS), 256, AT_SMEM>>>(
        ah, al, kh, kl, vh, vl, at);

    // 6) split attention output, then O projection
    {
        const int xn4 = MROWS * DMODEL / 4;
        split_kernel<<<xn4 / 256, 256>>>((const float4*)at, ah, al, xn4);
    }
    gemm_tc_kernel<<<gg, 256, GM_SMEM>>>(ah, al, wh + 3 * WSZ, wl + 3 * WSZ, out, 0);
}

// round 9
// speedup vs baseline: 3.7167x; 1.0416x over previous
#include <cuda_runtime.h>
#include <cuda_bf16.h>
#include <math.h>
#include <stdint.h>

// Problem constants
#define BATCH 2
#define SEQ 2048
#define DMODEL 2048
#define NHEADS 16
#define HEADDIM 128
#define CACHE 2048
#define TTOT 4096           // CACHE + SEQ
#define MROWS (BATCH*SEQ)   // 4096
#define KVELEMS (BATCH*NHEADS*TTOT*HEADDIM)  // 16777216

// ---------------------------------------------------------------------------
// Scratch (device globals; no allocations allowed)
// ---------------------------------------------------------------------------
__device__ __nv_bfloat16 g_ah[MROWS * DMODEL];   // x hi, later attn-out hi
__device__ __nv_bfloat16 g_al[MROWS * DMODEL];   // x lo, later attn-out lo
__device__ __nv_bfloat16 g_qh[MROWS * DMODEL];
__device__ __nv_bfloat16 g_ql[MROWS * DMODEL];
__device__ __nv_bfloat16 g_wh[4][DMODEL * DMODEL];
__device__ __nv_bfloat16 g_wl[4][DMODEL * DMODEL];
__device__ __nv_bfloat16 g_kh[KVELEMS];
__device__ __nv_bfloat16 g_kl[KVELEMS];
__device__ __nv_bfloat16 g_vh[KVELEMS];
__device__ __nv_bfloat16 g_vl[KVELEMS];

// ---------------------------------------------------------------------------
// Helpers
// ---------------------------------------------------------------------------
__device__ __forceinline__ uint32_t smem_u32(const void* p) {
    uint32_t a;
    asm("{ .reg .u64 t; cvta.to.shared.u64 t, %1; cvt.u32.u64 %0, t; }" : "=r"(a) : "l"(p));
    return a;
}
__device__ __forceinline__ void cp16(void* dst_smem, const void* src) {
    uint32_t d = smem_u32(dst_smem);
    asm volatile("cp.async.cg.shared.global [%0], [%1], 16;" :: "r"(d), "l"(src) : "memory");
}
__device__ __forceinline__ void cp_commit() {
    asm volatile("cp.async.commit_group;" ::: "memory");
}
__device__ __forceinline__ void cp_wait1() {
    asm volatile("cp.async.wait_group 1;" ::: "memory");
}
__device__ __forceinline__ void cp_wait0() {
    asm volatile("cp.async.wait_group 0;" ::: "memory");
}
// D += A*B : m16n8k16 bf16, fp32 accum
__device__ __forceinline__ void mma16816(float* c, const uint32_t* a, const uint32_t* b) {
    asm volatile(
        "mma.sync.aligned.m16n8k16.row.col.f32.bf16.bf16.f32 "
        "{%0,%1,%2,%3}, {%4,%5,%6,%7}, {%8,%9}, {%0,%1,%2,%3};"
        : "+f"(c[0]), "+f"(c[1]), "+f"(c[2]), "+f"(c[3])
        : "r"(a[0]), "r"(a[1]), "r"(a[2]), "r"(a[3]), "r"(b[0]), "r"(b[1]));
}
__device__ __forceinline__ void ldsm_x4(uint32_t* r, uint32_t saddr) {
    asm volatile("ldmatrix.sync.aligned.m8n8.x4.shared.b16 {%0,%1,%2,%3}, [%4];"
                 : "=r"(r[0]), "=r"(r[1]), "=r"(r[2]), "=r"(r[3]) : "r"(saddr));
}
__device__ __forceinline__ void ldsm_x2_trans(uint32_t& r0, uint32_t& r1, uint32_t saddr) {
    asm volatile("ldmatrix.sync.aligned.m8n8.x2.trans.shared.b16 {%0,%1}, [%2];"
                 : "=r"(r0), "=r"(r1) : "r"(saddr));
}
// pack pair of floats to bf16x2 hi and residual lo
__device__ __forceinline__ void packsplit(float p0, float p1, uint32_t& hi, uint32_t& lo) {
    __nv_bfloat162 h = __floats2bfloat162_rn(p0, p1);
    float f0 = __low2float(h), f1 = __high2float(h);
    __nv_bfloat162 g = __floats2bfloat162_rn(p0 - f0, p1 - f1);
    hi = *(uint32_t*)&h;
    lo = *(uint32_t*)&g;
}

// ---------------------------------------------------------------------------
// fp32 -> bf16 hi/lo split (x and weights only)
// ---------------------------------------------------------------------------
__global__ __launch_bounds__(256) void split_kernel(
    const float4* __restrict__ in, __nv_bfloat16* __restrict__ hi,
    __nv_bfloat16* __restrict__ lo, int n4)
{
    int i = blockIdx.x * blockDim.x + threadIdx.x;
    if (i >= n4) return;
    float4 v = in[i];
    union { __nv_bfloat16 h[4]; uint2 u; } H, L;
    float f[4] = {v.x, v.y, v.z, v.w};
#pragma unroll
    for (int j = 0; j < 4; j++) {
        __nv_bfloat16 h = __float2bfloat16_rn(f[j]);
        H.h[j] = h;
        L.h[j] = __float2bfloat16_rn(f[j] - __bfloat162float(h));
    }
    *(uint2*)(hi + (long)i * 4) = H.u;
    *(uint2*)(lo + (long)i * 4) = L.u;
}

// ---------------------------------------------------------------------------
// Cache copy + fused split: cached_k/v -> k_out/v_out fp32 AND kh/kl/vh/vl bf16
// ---------------------------------------------------------------------------
__global__ __launch_bounds__(256) void copy_cache_kernel(
    const float4* __restrict__ ck, const float4* __restrict__ cv,
    float4* __restrict__ ko, float4* __restrict__ vo,
    __nv_bfloat16* __restrict__ kh, __nv_bfloat16* __restrict__ kl,
    __nv_bfloat16* __restrict__ vh, __nv_bfloat16* __restrict__ vl)
{
    int i = blockIdx.x * blockDim.x + threadIdx.x;
    const int N4 = BATCH * NHEADS * CACHE * HEADDIM / 4;
    if (i >= N4) return;
    const int per_bh = CACHE * HEADDIM / 4;
    int bh  = i / per_bh;
    int rem = i - bh * per_bh;
    long dst = (long)bh * (TTOT * HEADDIM / 4) + rem;

    float4 k = ck[i], v = cv[i];
    ko[dst] = k;
    vo[dst] = v;

    union { __nv_bfloat16 h[4]; uint2 u; } KH, KL, VH, VL;
    float kf[4] = {k.x, k.y, k.z, k.w};
    float vf[4] = {v.x, v.y, v.z, v.w};
#pragma unroll
    for (int j = 0; j < 4; j++) {
        __nv_bfloat16 h = __float2bfloat16_rn(kf[j]);
        KH.h[j] = h;
        KL.h[j] = __float2bfloat16_rn(kf[j] - __bfloat162float(h));
        __nv_bfloat16 g = __float2bfloat16_rn(vf[j]);
        VH.h[j] = g;
        VL.h[j] = __float2bfloat16_rn(vf[j] - __bfloat162float(g));
    }
    *(uint2*)(kh + dst * 4) = KH.u;
    *(uint2*)(kl + dst * 4) = KL.u;
    *(uint2*)(vh + dst * 4) = VH.u;
    *(uint2*)(vl + dst * 4) = VL.u;
}

// ---------------------------------------------------------------------------
// HMMA GEMM: C[m,n] = sum_k A[m,k]*B[n,k]  (fp32 via bf16 hi/lo, 3 MMAs)
// ldmatrix.x4 fragment loads. Fused hi/lo output split in epilogue.
// mode 0: bf16 hi/lo row-major only (Q projection)
// mode 1: fp32 + bf16 hi/lo scatter into (B,H,TTOT,Dh) at t=CACHE+s (K/V)
// mode 2: fp32 row-major only (O projection)
// ---------------------------------------------------------------------------
#define GM_RS    80
#define GM_MAT   (128 * GM_RS)
#define GM_BUF   (4 * GM_MAT)
#define GM_SMEM  (2 * GM_BUF)
#define GM_KCH   64

__device__ __forceinline__ void gm_issue_chunk(
    char* buf, const __nv_bfloat16* Ah, const __nv_bfloat16* Al,
    const __nv_bfloat16* Bh, const __nv_bfloat16* Bl,
    long m0, long n0, int k0, int tid)
{
    const int row = tid >> 2;
    const int seg = tid & 3;
#pragma unroll
    for (int it = 0; it < 2; it++) {
        int rr = row + it * 64;
        long off = (long)k0 + seg * 8;
        cp16(buf + 0 * GM_MAT + rr * GM_RS + seg * 16, Ah + (m0 + rr) * DMODEL + off);
        cp16(buf + 1 * GM_MAT + rr * GM_RS + seg * 16, Al + (m0 + rr) * DMODEL + off);
        cp16(buf + 2 * GM_MAT + rr * GM_RS + seg * 16, Bh + (n0 + rr) * DMODEL + off);
        cp16(buf + 3 * GM_MAT + rr * GM_RS + seg * 16, Bl + (n0 + rr) * DMODEL + off);
    }
    cp_commit();
}

__global__ __launch_bounds__(256, 1)
void gemm_tc_kernel(const __nv_bfloat16* __restrict__ Ah,
                    const __nv_bfloat16* __restrict__ Al,
                    const __nv_bfloat16* __restrict__ Bh,
                    const __nv_bfloat16* __restrict__ Bl,
                    float* __restrict__ C,
                    __nv_bfloat16* __restrict__ Ch,
                    __nv_bfloat16* __restrict__ Cl,
                    int mode)
{
    extern __shared__ char dsm[];
    const int tid  = threadIdx.x;
    const int wid  = tid >> 5;
    const int l    = tid & 31;
    const int wm   = wid >> 2;
    const int wn   = wid & 3;
    const long m0 = (long)blockIdx.y * 128;
    const long n0 = (long)blockIdx.x * 128;
    const uint32_t dsm32 = smem_u32(dsm);

    const int fr = l >> 2;
    const int fq = (l & 3) * 2;

    // ldmatrix lane addressing
    const uint32_t aoff = (uint32_t)((wm * 64 + (l & 15)) * GM_RS + ((l >> 4) << 4));
    const uint32_t boff = (uint32_t)(2 * GM_MAT +
        (wn * 32 + ((l >> 4) << 3) + (l & 7)) * GM_RS + (((l >> 3) & 1) << 4));

    float acc[4][4][4];
#pragma unroll
    for (int i = 0; i < 4; i++)
#pragma unroll
        for (int j = 0; j < 4; j++)
#pragma unroll
            for (int t = 0; t < 4; t++) acc[i][j][t] = 0.f;

    gm_issue_chunk(dsm, Ah, Al, Bh, Bl, m0, n0, 0, tid);

    for (int c = 0; c < GM_KCH; c++) {
        if (c + 1 < GM_KCH)
            gm_issue_chunk(dsm + ((c + 1) & 1) * GM_BUF, Ah, Al, Bh, Bl,
                           m0, n0, (c + 1) * 32, tid);
        if (c + 1 < GM_KCH) cp_wait1(); else cp_wait0();
        __syncthreads();

        const uint32_t sb = dsm32 + (uint32_t)((c & 1) * GM_BUF);
#pragma unroll
        for (int kk = 0; kk < 32; kk += 16) {
            uint32_t ah4[4][4], al4[4][4];
#pragma unroll
            for (int mt = 0; mt < 4; mt++) {
                ldsm_x4(ah4[mt], sb + aoff + mt * 16 * GM_RS + kk * 2);
                ldsm_x4(al4[mt], sb + GM_MAT + aoff + mt * 16 * GM_RS + kk * 2);
            }
#pragma unroll
            for (int p = 0; p < 2; p++) {
                uint32_t bh4[4], bl4[4];
                ldsm_x4(bh4, sb + boff + p * 16 * GM_RS + kk * 2);
                ldsm_x4(bl4, sb + GM_MAT + boff + p * 16 * GM_RS + kk * 2);
#pragma unroll
                for (int mt = 0; mt < 4; mt++) {
                    mma16816(acc[mt][2 * p],     ah4[mt], bh4);
                    mma16816(acc[mt][2 * p],     ah4[mt], bl4);
                    mma16816(acc[mt][2 * p],     al4[mt], bh4);
                    mma16816(acc[mt][2 * p + 1], ah4[mt], bh4 + 2);
                    mma16816(acc[mt][2 * p + 1], ah4[mt], bl4 + 2);
                    mma16816(acc[mt][2 * p + 1], al4[mt], bh4 + 2);
                }
            }
        }
        __syncthreads();
    }

    // Epilogue
#pragma unroll
    for (int mt = 0; mt < 4; mt++) {
#pragma unroll
        for (int nt = 0; nt < 4; nt++) {
            long m = m0 + wm * 64 + mt * 16 + fr;
            int  n = (int)n0 + wn * 32 + nt * 8 + fq;
            float* a = acc[mt][nt];
            if (mode == 1) {
                int b = (int)(m >> 11), s = (int)(m & 2047);
                int h = n >> 7, dh = n & 127;
                long base = ((long)(b * NHEADS + h) * TTOT + CACHE + s) * HEADDIM + dh;
                *(float2*)(C + base) = make_float2(a[0], a[1]);
                *(float2*)(C + base + 8 * HEADDIM) = make_float2(a[2], a[3]);
                uint32_t h0, l0, h1, l1;
                packsplit(a[0], a[1], h0, l0);
                packsplit(a[2], a[3], h1, l1);
                *(uint32_t*)(Ch + base) = h0;
                *(uint32_t*)(Cl + base) = l0;
                *(uint32_t*)(Ch + base + 8 * HEADDIM) = h1;
                *(uint32_t*)(Cl + base + 8 * HEADDIM) = l1;
            } else if (mode == 0) {
                long e = m * DMODEL + n;
                uint32_t h0, l0, h1, l1;
                packsplit(a[0], a[1], h0, l0);
                packsplit(a[2], a[3], h1, l1);
                *(uint32_t*)(Ch + e) = h0;
                *(uint32_t*)(Cl + e) = l0;
                *(uint32_t*)(Ch + e + 8 * DMODEL) = h1;
                *(uint32_t*)(Cl + e + 8 * DMODEL) = l1;
            } else {
                long e = m * DMODEL + n;
                *(float2*)(C + e) = make_float2(a[0], a[1]);
                *(float2*)(C + e + 8 * DMODEL) = make_float2(a[2], a[3]);
            }
        }
    }
}

// ---------------------------------------------------------------------------
// Flash attention on HMMA (bf16 hi/lo, fp32 accum), ldmatrix frag loads.
// CTA: one (b,h), 128 query rows. 8 warps x 16 rows. BT=64 keys/iter.
// Epilogue writes bf16 hi/lo directly (consumed by O projection).
// ---------------------------------------------------------------------------
#define AT_RS    272
#define AT_QL    34816
#define AT_STG0  69632
#define AT_STGSZ 69632
#define AT_KL    17408
#define AT_VH    34816
#define AT_VL    52224
#define AT_SMEM  208896
#define AT_NIT   (TTOT / 64)

__device__ __forceinline__ void at_issue_kv(
    char* dsm, const __nv_bfloat16* Kh, const __nv_bfloat16* Kl,
    const __nv_bfloat16* Vh, const __nv_bfloat16* Vl,
    long kvoff, int it, int tid)
{
    char* stg = dsm + AT_STG0 + (it & 1) * AT_STGSZ;
    const int t0 = it * 64;
#pragma unroll
    for (int i = 0; i < 16; i++) {
        int idx = tid + i * 256;
        int mat = idx >> 10;
        int row = (idx >> 4) & 63;
        int ch  = idx & 15;
        const __nv_bfloat16* src;
        if      (mat == 0) src = Kh;
        else if (mat == 1) src = Kl;
        else if (mat == 2) src = Vh;
        else               src = Vl;
        cp16(stg + mat * 17408 + row * AT_RS + ch * 16,
             src + kvoff + (long)(t0 + row) * HEADDIM + ch * 8);
    }
    cp_commit();
}

__global__ __launch_bounds__(256, 1) void attn_kernel(
    const __nv_bfloat16* __restrict__ Qh, const __nv_bfloat16* __restrict__ Ql,
    const __nv_bfloat16* __restrict__ Kh, const __nv_bfloat16* __restrict__ Kl,
    const __nv_bfloat16* __restrict__ Vh, const __nv_bfloat16* __restrict__ Vl,
    __nv_bfloat16* __restrict__ Oh, __nv_bfloat16* __restrict__ Ol)
{
    extern __shared__ char dsm[];
    const int tid = threadIdx.x;
    const int w  = tid >> 5;
    const int l  = tid & 31;
    const int fr = l >> 2;
    const int bh = blockIdx.y;
    const int b  = bh >> 4, h = bh & 15;
    const int s0 = blockIdx.x * 128;
    const uint32_t sbase = smem_u32(dsm);
    const float scale = 0.08838834764831845f;

    // ldmatrix lane addressing
    const uint32_t qoffm = (uint32_t)((w * 16 + (l & 15)) * AT_RS + ((l >> 4) << 4));
    const uint32_t koffm = (uint32_t)((((l >> 4) << 3) + (l & 7)) * AT_RS + (((l >> 3) & 1) << 4));

    // Issue Q tiles (hi+lo) + KV stage 0 + KV stage 1
    {
        const long qoff = ((long)b * SEQ + s0) * DMODEL + h * HEADDIM;
#pragma unroll
        for (int i = 0; i < 16; i++) {
            int idx = tid + i * 256;
            int mat = idx >> 11;
            int row = (idx >> 4) & 127;
            int ch  = idx & 15;
            const __nv_bfloat16* src = (mat ? Ql : Qh) + qoff + (long)row * DMODEL + ch * 8;
            cp16(dsm + mat * AT_QL + row * AT_RS + ch * 16, src);
        }
    }
    const long kvoff = (long)bh * TTOT * HEADDIM;
    at_issue_kv(dsm, Kh, Kl, Vh, Vl, kvoff, 0, tid);
    at_issue_kv(dsm, Kh, Kl, Vh, Vl, kvoff, 1, tid);

    float m_lo = -INFINITY, m_hi = -INFINITY, l_lo = 0.f, l_hi = 0.f;
    float oacc[16][4];
#pragma unroll
    for (int i = 0; i < 16; i++)
#pragma unroll
        for (int j = 0; j < 4; j++) oacc[i][j] = 0.f;

    for (int it = 0; it < AT_NIT; it++) {
        if (it + 1 < AT_NIT) cp_wait1(); else cp_wait0();
        __syncthreads();

        const uint32_t stg32 = sbase + AT_STG0 + (uint32_t)((it & 1) * AT_STGSZ);

        // ---- S = Q K^T ----
        float sacc[8][4];
#pragma unroll
        for (int i = 0; i < 8; i++)
#pragma unroll
            for (int j = 0; j < 4; j++) sacc[i][j] = 0.f;

#pragma unroll
        for (int ks = 0; ks < 8; ks++) {
            uint32_t aH[4], aL[4];
            ldsm_x4(aH, sbase + qoffm + ks * 32);
            ldsm_x4(aL, sbase + AT_QL + qoffm + ks * 32);
#pragma unroll
            for (int p = 0; p < 4; p++) {
                uint32_t bH[4], bL[4];
                ldsm_x4(bH, stg32 + koffm + p * 16 * AT_RS + ks * 32);
                ldsm_x4(bL, stg32 + AT_KL + koffm + p * 16 * AT_RS + ks * 32);
                mma16816(sacc[2 * p],     aH, bH);
                mma16816(sacc[2 * p],     aH, bL);
                mma16816(sacc[2 * p],     aL, bH);
                mma16816(sacc[2 * p + 1], aH, bH + 2);
                mma16816(sacc[2 * p + 1], aH, bL + 2);
                mma16816(sacc[2 * p + 1], aL, bH + 2);
            }
        }

        // ---- online softmax (rows fr and fr+8 of this warp) ----
        float mx0 = -INFINITY, mx1 = -INFINITY;
#pragma unroll
        for (int nt = 0; nt < 8; nt++) {
#pragma unroll
            for (int j = 0; j < 4; j++) sacc[nt][j] *= scale;
            mx0 = fmaxf(mx0, fmaxf(sacc[nt][0], sacc[nt][1]));
            mx1 = fmaxf(mx1, fmaxf(sacc[nt][2], sacc[nt][3]));
        }
        mx0 = fmaxf(mx0, __shfl_xor_sync(0xffffffffu, mx0, 1));
        mx0 = fmaxf(mx0, __shfl_xor_sync(0xffffffffu, mx0, 2));
        mx1 = fmaxf(mx1, __shfl_xor_sync(0xffffffffu, mx1, 1));
        mx1 = fmaxf(mx1, __shfl_xor_sync(0xffffffffu, mx1, 2));
        float mn0 = fmaxf(m_lo, mx0), mn1 = fmaxf(m_hi, mx1);
        float al0 = __expf(m_lo - mn0), al1 = __expf(m_hi - mn1);
        float sm0 = 0.f, sm1 = 0.f;
#pragma unroll
        for (int nt = 0; nt < 8; nt++) {
            sacc[nt][0] = __expf(sacc[nt][0] - mn0);
            sacc[nt][1] = __expf(sacc[nt][1] - mn0);
            sacc[nt][2] = __expf(sacc[nt][2] - mn1);
            sacc[nt][3] = __expf(sacc[nt][3] - mn1);
            sm0 += sacc[nt][0] + sacc[nt][1];
            sm1 += sacc[nt][2] + sacc[nt][3];
        }
        sm0 += __shfl_xor_sync(0xffffffffu, sm0, 1);
        sm0 += __shfl_xor_sync(0xffffffffu, sm0, 2);
        sm1 += __shfl_xor_sync(0xffffffffu, sm1, 1);
        sm1 += __shfl_xor_sync(0xffffffffu, sm1, 2);
        l_lo = l_lo * al0 + sm0;  m_lo = mn0;
        l_hi = l_hi * al1 + sm1;  m_hi = mn1;

#pragma unroll
        for (int dt = 0; dt < 16; dt++) {
            oacc[dt][0] *= al0;  oacc[dt][1] *= al0;
            oacc[dt][2] *= al1;  oacc[dt][3] *= al1;
        }

        // ---- O += P V ----
        const uint32_t vbase = stg32 + AT_VH;
#pragma unroll
        for (int kt = 0; kt < 4; kt++) {
            uint32_t aPh[4], aPl[4];
            packsplit(sacc[2 * kt][0],     sacc[2 * kt][1],     aPh[0], aPl[0]);
            packsplit(sacc[2 * kt][2],     sacc[2 * kt][3],     aPh[1], aPl[1]);
            packsplit(sacc[2 * kt + 1][0], sacc[2 * kt + 1][1], aPh[2], aPl[2]);
            packsplit(sacc[2 * kt + 1][2], sacc[2 * kt + 1][3], aPh[3], aPl[3]);
            uint32_t vrow = vbase + (uint32_t)((kt * 16 + (l & 15)) * AT_RS);
#pragma unroll
            for (int dt = 0; dt < 16; dt++) {
                uint32_t bvh[2], bvl[2];
                ldsm_x2_trans(bvh[0], bvh[1], vrow + dt * 16);
                ldsm_x2_trans(bvl[0], bvl[1], vrow + AT_KL + dt * 16);
                mma16816(oacc[dt], aPh, bvh);
                mma16816(oacc[dt], aPh, bvl);
                mma16816(oacc[dt], aPl, bvh);
            }
        }

        __syncthreads();
        if (it + 2 < AT_NIT)
            at_issue_kv(dsm, Kh, Kl, Vh, Vl, kvoff, it + 2, tid);
    }

    // ---- epilogue: normalize + hi/lo split store to (B,S,DMODEL) ----
    float inv0 = 1.f / l_lo, inv1 = 1.f / l_hi;
    long r0 = ((long)b * SEQ + s0 + w * 16 + fr) * DMODEL + h * HEADDIM + (l & 3) * 2;
#pragma unroll
    for (int dt = 0; dt < 16; dt++) {
        uint32_t h0, l0, h1, l1;
        packsplit(oacc[dt][0] * inv0, oacc[dt][1] * inv0, h0, l0);
        packsplit(oacc[dt][2] * inv1, oacc[dt][3] * inv1, h1, l1);
        *(uint32_t*)(Oh + r0 + dt * 8) = h0;
        *(uint32_t*)(Ol + r0 + dt * 8) = l0;
        *(uint32_t*)(Oh + r0 + 8 * DMODEL + dt * 8) = h1;
        *(uint32_t*)(Ol + r0 + 8 * DMODEL + dt * 8) = l1;
    }
}

// ---------------------------------------------------------------------------
// kernel_launch
// Inputs: x, cached_k, cached_v, W_q, W_k, W_v, W_o
// Output: [ out (B,S,D) | k (B,H,TTOT,Dh) | v (B,H,TTOT,Dh) ]
// ---------------------------------------------------------------------------
extern "C" void kernel_launch(void* const* d_in, const int* in_sizes, int n_in,
                              void* d_out, int out_size)
{
    const float* x  = (const float*)d_in[0];
    const float* ck = (const float*)d_in[1];
    const float* cv = (const float*)d_in[2];
    const float* wts[4] = { (const float*)d_in[3], (const float*)d_in[4],
                            (const float*)d_in[5], (const float*)d_in[6] };

    float* out   = (float*)d_out;
    float* k_out = out + (long)MROWS * DMODEL;
    float* v_out = k_out + (long)KVELEMS;

    __nv_bfloat16 *ah, *al, *qh, *ql, *wh, *wl, *kh, *kl, *vh, *vl;
    cudaGetSymbolAddress((void**)&ah, g_ah);
    cudaGetSymbolAddress((void**)&al, g_al);
    cudaGetSymbolAddress((void**)&qh, g_qh);
    cudaGetSymbolAddress((void**)&ql, g_ql);
    cudaGetSymbolAddress((void**)&wh, g_wh);
    cudaGetSymbolAddress((void**)&wl, g_wl);
    cudaGetSymbolAddress((void**)&kh, g_kh);
    cudaGetSymbolAddress((void**)&kl, g_kl);
    cudaGetSymbolAddress((void**)&vh, g_vh);
    cudaGetSymbolAddress((void**)&vl, g_vl);

    // 1) copy KV cache into outputs + fused hi/lo split of cache rows
    {
        const int N4 = BATCH * NHEADS * CACHE * HEADDIM / 4;
        copy_cache_kernel<<<(N4 + 255) / 256, 256>>>(
            (const float4*)ck, (const float4*)cv, (float4*)k_out, (float4*)v_out,
            kh, kl, vh, vl);
    }

    // 2) hi/lo splits: x and the 4 weights
    {
        const int xn4 = MROWS * DMODEL / 4;
        split_kernel<<<xn4 / 256, 256>>>((const float4*)x, ah, al, xn4);
        const int wn4 = DMODEL * DMODEL / 4;
        for (int i = 0; i < 4; i++)
            split_kernel<<<wn4 / 256, 256>>>((const float4*)wts[i],
                                             wh + (long)i * DMODEL * DMODEL,
                                             wl + (long)i * DMODEL * DMODEL, wn4);
    }

    // 3) Q, K, V projections (HMMA, fused split epilogues)
    cudaFuncSetAttribute(gemm_tc_kernel, cudaFuncAttributeMaxDynamicSharedMemorySize,
                         GM_SMEM);
    dim3 gg(DMODEL / 128, MROWS / 128);  // (16, 32)
    const long WSZ = (long)DMODEL * DMODEL;
    gemm_tc_kernel<<<gg, 256, GM_SMEM>>>(ah, al, wh + 0 * WSZ, wl + 0 * WSZ,
                                         nullptr, qh, ql, 0);
    gemm_tc_kernel<<<gg, 256, GM_SMEM>>>(ah, al, wh + 1 * WSZ, wl + 1 * WSZ,
                                         k_out, kh, kl, 1);
    gemm_tc_kernel<<<gg, 256, GM_SMEM>>>(ah, al, wh + 2 * WSZ, wl + 2 * WSZ,
                                         v_out, vh, vl, 1);

    // 4) attention (HMMA), writes hi/lo into ah/al (x no longer needed)
    cudaFuncSetAttribute(attn_kernel, cudaFuncAttributeMaxDynamicSharedMemorySize,
                         AT_SMEM);
    attn_kernel<<<dim3(SEQ / 128, BATCH * NHEADS), 256, AT_SMEM>>>(
        qh, ql, kh, kl, vh, vl, ah, al);

    // 5) O projection
    gemm_tc_kernel<<<gg, 256, GM_SMEM>>>(ah, al, wh + 3 * WSZ, wl + 3 * WSZ,
                                         out, nullptr, nullptr, 2);
}